// round 6
// baseline (speedup 1.0000x reference)
#include <cuda_runtime.h>
#include <cuda_bf16.h>
#include <stdint.h>

// Problem constants (fixed shapes)
#define NN      8192        // nodes
#define NE      262144      // edges
#define CIN     512
#define COUT    512
#define NITEMS  (NE + NN)   // edges + self loops (270336 = 264*1024)
#define BM_WORDS ((size_t)NN * NN / 32)   // 2,097,152 words = 8 MB bitmap

// ---------------- device scratch (no allocations allowed) ----------------
__device__ unsigned g_bitmap[BM_WORDS];      // 8 MB adjacency bitmap
__device__ int      g_deg[NN];
__device__ int      g_off[NN + 1];
__device__ float    g_dinv[NN];
__device__ int      g_cols[NITEMS];
__device__ unsigned short g_rank[NITEMS];    // slot within row; 0xFFFF = duplicate
__device__ float    g_h[(size_t)NN * COUT];  // 16 MB: h = xW^T + b
__device__ int      g_is64;

// ---------------- clear bitmap + degree, fused dtype detection ----------------
// Detection: if int64 (LE), high words of ids are 0 (ids < 8192). If int32,
// odd words are random ids: P(128 random ids all zero) = 8192^-128 ~ 0.
__global__ void k_clear(const unsigned* __restrict__ e) {
    size_t i = (size_t)blockIdx.x * blockDim.x + threadIdx.x;
    if (i < BM_WORDS / 4) ((uint4*)g_bitmap)[i] = make_uint4(0u, 0u, 0u, 0u);
    if (i < NN) g_deg[i] = 0;
    if (blockIdx.x == 0) {
        unsigned v = (threadIdx.x < 128) ? e[threadIdx.x * 2 + 1] : 0u;
        int any = __syncthreads_or(v != 0u);
        if (threadIdx.x == 0) g_is64 = !any;
    }
}

__device__ __forceinline__ void edge_rc(const void* eidx, int is64, int i, int& r, int& c) {
    if (i < NE) {
        if (is64) {
            r = (int)((const long long*)eidx)[i];
            c = (int)((const long long*)eidx)[NE + i];
        } else {
            r = ((const int*)eidx)[i];
            c = ((const int*)eidx)[NE + i];
        }
    } else {
        r = c = i - NE;   // self loop
    }
}

// ---------------- mark distinct edges, count degree, record rank ----------------
// 4 edges per thread for MLP on the atomic round-trips.
__global__ __launch_bounds__(256)
void k_mark(const void* __restrict__ eidx) {
    int base = (blockIdx.x * 256 + threadIdx.x) * 4;
    if (base >= NITEMS) return;
    int is64 = g_is64;
    int r[4], c[4];
    unsigned old[4];
    #pragma unroll
    for (int e = 0; e < 4; e++) edge_rc(eidx, is64, base + e, r[e], c[e]);
    // batch the 4 independent atomicOr's (overlapped in flight)
    #pragma unroll
    for (int e = 0; e < 4; e++) {
        size_t idx = (size_t)r[e] * NN + c[e];
        old[e] = atomicOr(&g_bitmap[idx >> 5], 1u << (idx & 31)) & (1u << (idx & 31));
    }
    #pragma unroll
    for (int e = 0; e < 4; e++) {
        unsigned short rk = 0xFFFFu;
        if (!old[e]) rk = (unsigned short)atomicAdd(&g_deg[r[e]], 1);
        g_rank[base + e] = rk;
    }
}

// ---------------- exclusive scan of degrees -> CSR offsets, dinv ----------------
// 1024 threads x 8 values, warp-shuffle two-level scan (2 barriers).
__global__ void k_scan() {
    __shared__ int wsum[32];
    int t = threadIdx.x;
    int lane = t & 31, wid = t >> 5;
    int v[8];
    int s = 0;
    #pragma unroll
    for (int i = 0; i < 8; i++) { v[i] = g_deg[t * 8 + i]; s += v[i]; }

    int x = s;
    #pragma unroll
    for (int off = 1; off < 32; off <<= 1) {
        int y = __shfl_up_sync(0xffffffffu, x, off);
        if (lane >= off) x += y;
    }
    if (lane == 31) wsum[wid] = x;
    __syncthreads();
    if (wid == 0) {
        int y = wsum[lane];
        #pragma unroll
        for (int off = 1; off < 32; off <<= 1) {
            int z = __shfl_up_sync(0xffffffffu, y, off);
            if (lane >= off) y += z;
        }
        wsum[lane] = y;
    }
    __syncthreads();

    int excl = (wid ? wsum[wid - 1] : 0) + x - s;
    #pragma unroll
    for (int i = 0; i < 8; i++) {
        int n = t * 8 + i;
        g_off[n]  = excl;
        g_dinv[n] = rsqrtf((float)v[i]);   // deg >= 1 (self loop)
        excl += v[i];
    }
    if (t == 1023) g_off[NN] = wsum[31];
}

// ---------------- fill CSR column list (no atomics: off[r] + rank) ----------------
__global__ __launch_bounds__(256)
void k_fill(const void* __restrict__ eidx) {
    int base = (blockIdx.x * 256 + threadIdx.x) * 4;
    if (base >= NITEMS) return;
    int is64 = g_is64;
    #pragma unroll
    for (int e = 0; e < 4; e++) {
        int i = base + e;
        unsigned short rk = g_rank[i];
        if (rk == 0xFFFFu) continue;
        int r, c;
        edge_rc(eidx, is64, i, r, c);
        g_cols[g_off[r] + rk] = c;
    }
}

// ---------------- tensor-core GEMM: h = x W^T + b via bf16 3-term split ----------------
// x*W ~= b1*W1 + b1*W2 + b2*W1 (error ~2^-18 per product, fp32 accumulate).
// Block tile 128x128, BK=32, 256 threads = 8 warps, warp tile 64x32.
// ldmatrix.x4 fragment loads (pad-40 stride -> conflict-free: banks m*20 mod 32),
// register-prefetch double buffering of global loads.
#define BKP 40   // smem row stride in bf16 elems

__device__ __forceinline__ void mma_bf16(float* c, const unsigned* a, const unsigned* b) {
    asm volatile(
        "mma.sync.aligned.m16n8k16.row.col.f32.bf16.bf16.f32 "
        "{%0,%1,%2,%3}, {%4,%5,%6,%7}, {%8,%9}, {%0,%1,%2,%3};"
        : "+f"(c[0]), "+f"(c[1]), "+f"(c[2]), "+f"(c[3])
        : "r"(a[0]), "r"(a[1]), "r"(a[2]), "r"(a[3]), "r"(b[0]), "r"(b[1]));
}

__device__ __forceinline__ void ldsm4(unsigned* r, unsigned addr) {
    asm volatile("ldmatrix.sync.aligned.m8n8.x4.shared.b16 {%0,%1,%2,%3}, [%4];"
        : "=r"(r[0]), "=r"(r[1]), "=r"(r[2]), "=r"(r[3]) : "r"(addr));
}

__device__ __forceinline__ unsigned pack_split(float x, float y, unsigned& lo_pack) {
    __nv_bfloat16 hx = __float2bfloat16(x);
    __nv_bfloat16 hy = __float2bfloat16(y);
    __nv_bfloat16 lx = __float2bfloat16(x - __bfloat162float(hx));
    __nv_bfloat16 ly = __float2bfloat16(y - __bfloat162float(hy));
    __nv_bfloat162 hi2 = __nv_bfloat162(hx, hy);
    __nv_bfloat162 lo2 = __nv_bfloat162(lx, ly);
    lo_pack = *(unsigned*)&lo2;
    return *(unsigned*)&hi2;
}

__global__ __launch_bounds__(256)
void k_gemm_tc(const float* __restrict__ A, const float* __restrict__ W,
               const float* __restrict__ bias, float* __restrict__ C) {
    __shared__ __nv_bfloat16 sA1[128 * BKP];
    __shared__ __nv_bfloat16 sA2[128 * BKP];
    __shared__ __nv_bfloat16 sB1[128 * BKP];
    __shared__ __nv_bfloat16 sB2[128 * BKP];

    int tid = threadIdx.x;
    int m0 = blockIdx.y * 128;
    int n0 = blockIdx.x * 128;
    int lane = tid & 31, w = tid >> 5;
    int wm = (w & 1) * 64;       // warp row offset
    int wn = (w >> 1) * 32;      // warp col offset
    int g  = lane >> 2;          // 0..7
    int tg = lane & 3;           // 0..3

    // ldmatrix per-lane address components
    int jj = lane >> 3, jr = lane & 7;
    unsigned sA1b = (unsigned)__cvta_generic_to_shared(sA1);
    unsigned sA2b = (unsigned)__cvta_generic_to_shared(sA2);
    unsigned sB1b = (unsigned)__cvta_generic_to_shared(sB1);
    unsigned sB2b = (unsigned)__cvta_generic_to_shared(sB2);
    unsigned aoff = (unsigned)(((wm + (jj & 1) * 8 + jr) * BKP + (jj >> 1) * 8) * 2);
    unsigned boff = (unsigned)(((wn + (jj >> 1) * 8 + jr) * BKP + (jj & 1) * 8) * 2);
    unsigned a1addr = sA1b + aoff, a2addr = sA2b + aoff;
    unsigned b1addr = sB1b + boff, b2addr = sB2b + boff;

    float acc[4][4][4];
    #pragma unroll
    for (int mi = 0; mi < 4; mi++)
        #pragma unroll
        for (int ni = 0; ni < 4; ni++)
            #pragma unroll
            for (int q = 0; q < 4; q++) acc[mi][ni][q] = 0.f;

    int lr = tid >> 3;          // 0..31
    int lc = (tid & 7) * 4;     // 0..28
    const float* Ap = A + (size_t)(m0 + lr) * CIN + lc;
    const float* Wp = W + (size_t)(n0 + lr) * CIN + lc;

    float4 va[4], vb[4];
    #pragma unroll
    for (int rr = 0; rr < 4; rr++) {
        va[rr] = *(const float4*)(Ap + (size_t)rr * 32 * CIN);
        vb[rr] = *(const float4*)(Wp + (size_t)rr * 32 * CIN);
    }

    #pragma unroll 1
    for (int kt = 0; kt < CIN; kt += 32) {
        // convert current prefetch into smem
        #pragma unroll
        for (int rr = 0; rr < 4; rr++) {
            int r = lr + rr * 32;
            unsigned l0, l1;
            unsigned h0 = pack_split(va[rr].x, va[rr].y, l0);
            unsigned h1 = pack_split(va[rr].z, va[rr].w, l1);
            *(uint2*)&sA1[r * BKP + lc] = make_uint2(h0, h1);
            *(uint2*)&sA2[r * BKP + lc] = make_uint2(l0, l1);
            h0 = pack_split(vb[rr].x, vb[rr].y, l0);
            h1 = pack_split(vb[rr].z, vb[rr].w, l1);
            *(uint2*)&sB1[r * BKP + lc] = make_uint2(h0, h1);
            *(uint2*)&sB2[r * BKP + lc] = make_uint2(l0, l1);
        }
        // issue next tile's global loads (hidden under compute)
        if (kt + 32 < CIN) {
            #pragma unroll
            for (int rr = 0; rr < 4; rr++) {
                va[rr] = *(const float4*)(Ap + (size_t)rr * 32 * CIN + kt + 32);
                vb[rr] = *(const float4*)(Wp + (size_t)rr * 32 * CIN + kt + 32);
            }
        }
        __syncthreads();

        #pragma unroll
        for (int ks = 0; ks < 2; ks++) {
            unsigned kb = (unsigned)(ks * 16 * 2);   // byte offset within row
            unsigned af[4][4], bf[2][4], bg[2][4];
            #pragma unroll
            for (int mi = 0; mi < 4; mi++)
                ldsm4(af[mi], a1addr + (unsigned)(mi * 16 * BKP * 2) + kb);
            #pragma unroll
            for (int p = 0; p < 2; p++)
                ldsm4(bf[p], b1addr + (unsigned)(p * 16 * BKP * 2) + kb);
            #pragma unroll
            for (int mi = 0; mi < 4; mi++)
                #pragma unroll
                for (int ni = 0; ni < 4; ni++)
                    mma_bf16(acc[mi][ni], af[mi], &bf[ni >> 1][(ni & 1) * 2]);  // hi*hi
            #pragma unroll
            for (int p = 0; p < 2; p++)
                ldsm4(bg[p], b2addr + (unsigned)(p * 16 * BKP * 2) + kb);
            #pragma unroll
            for (int mi = 0; mi < 4; mi++)
                #pragma unroll
                for (int ni = 0; ni < 4; ni++)
                    mma_bf16(acc[mi][ni], af[mi], &bg[ni >> 1][(ni & 1) * 2]);  // hi*lo
            #pragma unroll
            for (int mi = 0; mi < 4; mi++)
                ldsm4(af[mi], a2addr + (unsigned)(mi * 16 * BKP * 2) + kb);
            #pragma unroll
            for (int mi = 0; mi < 4; mi++)
                #pragma unroll
                for (int ni = 0; ni < 4; ni++)
                    mma_bf16(acc[mi][ni], af[mi], &bf[ni >> 1][(ni & 1) * 2]);  // lo*hi
        }
        __syncthreads();
    }

    // epilogue: add bias, write fp32
    #pragma unroll
    for (int mi = 0; mi < 4; mi++) {
        int r0 = m0 + wm + mi * 16 + g;
        #pragma unroll
        for (int ni = 0; ni < 4; ni++) {
            int col = n0 + wn + ni * 8 + tg * 2;
            float b0 = bias[col], b1 = bias[col + 1];
            float* p0 = C + (size_t)r0 * COUT + col;
            float* p1 = C + (size_t)(r0 + 8) * COUT + col;
            p0[0] = acc[mi][ni][0] + b0;
            p0[1] = acc[mi][ni][1] + b1;
            p1[0] = acc[mi][ni][2] + b0;
            p1[1] = acc[mi][ni][3] + b1;
        }
    }
}

// ---------------- aggregation: out[r] = dinv[r] * sum_{c in N(r)} dinv[c] * h[c] ----------------
__global__ __launch_bounds__(128)
void k_agg(const float* __restrict__ h, float* __restrict__ out) {
    __shared__ int   sc[256];
    __shared__ float sd[256];
    int r = blockIdx.x;
    int t = threadIdx.x;
    int beg = g_off[r], end = g_off[r + 1];
    float4 acc = make_float4(0.f, 0.f, 0.f, 0.f);

    for (int base = beg; base < end; base += 256) {
        int cnt = min(256, end - base);
        for (int j = t; j < cnt; j += 128) {
            int c = g_cols[base + j];
            sc[j] = c;
            sd[j] = g_dinv[c];
        }
        __syncthreads();
        #pragma unroll 4
        for (int j = 0; j < cnt; j++) {
            const float4* hv = (const float4*)(h + (size_t)sc[j] * COUT);
            float s = sd[j];
            float4 v = hv[t];
            acc.x = fmaf(s, v.x, acc.x);
            acc.y = fmaf(s, v.y, acc.y);
            acc.z = fmaf(s, v.z, acc.z);
            acc.w = fmaf(s, v.w, acc.w);
        }
        __syncthreads();
    }

    float dr = g_dinv[r];
    ((float4*)(out + (size_t)r * COUT))[t] =
        make_float4(dr * acc.x, dr * acc.y, dr * acc.z, dr * acc.w);
}

// ---------------- launch ----------------
extern "C" void kernel_launch(void* const* d_in, const int* in_sizes, int n_in,
                              void* d_out, int out_size) {
    const float* x    = (const float*)d_in[0];
    const void*  eidx = d_in[1];
    const float* W    = (const float*)d_in[2];
    const float* b    = (const float*)d_in[3];
    float* out = (float*)d_out;

    float* h_ptr;
    cudaGetSymbolAddress((void**)&h_ptr, g_h);

    // 1. clear bitmap + degrees (+ dtype detect in block 0)
    {
        int blocks = (int)((BM_WORDS / 4 + 255) / 256);   // 2048
        k_clear<<<blocks, 256>>>((const unsigned*)eidx);
    }
    // 2. mark distinct edges + degree + rank (4 edges/thread)
    k_mark<<<NITEMS / 1024, 256>>>(eidx);
    // 3. scan -> CSR offsets, dinv
    k_scan<<<1, 1024>>>();
    // 4. fill CSR cols (no atomics)
    k_fill<<<NITEMS / 1024, 256>>>(eidx);
    // 5. h = x W^T + b  (immediately before agg: h stays L2-hot)
    {
        dim3 grid(COUT / 128, NN / 128);  // (4, 64)
        k_gemm_tc<<<grid, 256>>>(x, W, b, h_ptr);
    }
    // 6. aggregate
    k_agg<<<NN, 128>>>(h_ptr, out);
}

// round 8
// speedup vs baseline: 1.0158x; 1.0158x over previous
#include <cuda_runtime.h>
#include <cuda_bf16.h>
#include <stdint.h>

// Problem constants (fixed shapes)
#define NN      8192        // nodes
#define NE      262144      // edges
#define CIN     512
#define COUT    512
#define NITEMS  (NE + NN)   // 270336 = 264*1024
#define BM_WORDS ((size_t)NN * NN / 32)   // 8 MB bitmap

// ---------------- device scratch (no allocations allowed) ----------------
__device__ unsigned g_bitmap[BM_WORDS];
__device__ int      g_deg[NN];
__device__ int      g_off[NN + 1];
__device__ float    g_dinv[NN];
__device__ int      g_cols[NITEMS];
__device__ unsigned short g_rank[NITEMS];    // slot within row; 0xFFFF = duplicate
__device__ unsigned g_rc[NITEMS];            // packed r | c<<16
__device__ float    g_h[(size_t)NN * COUT];  // 16 MB: h = xW^T + b
__device__ int      g_is64;
// split-bf16 operands for the tensor GEMM
__device__ __align__(16) __nv_bfloat16 g_xhi[(size_t)NN * CIN];
__device__ __align__(16) __nv_bfloat16 g_xlo[(size_t)NN * CIN];
__device__ __align__(16) __nv_bfloat16 g_whi[(size_t)COUT * CIN];
__device__ __align__(16) __nv_bfloat16 g_wlo[(size_t)COUT * CIN];

// ---------------- split helpers ----------------
__device__ __forceinline__ unsigned pack_split(float x, float y, unsigned& lo_pack) {
    __nv_bfloat16 hx = __float2bfloat16(x);
    __nv_bfloat16 hy = __float2bfloat16(y);
    __nv_bfloat16 lx = __float2bfloat16(x - __bfloat162float(hx));
    __nv_bfloat16 ly = __float2bfloat16(y - __bfloat162float(hy));
    __nv_bfloat162 hi2 = __nv_bfloat162(hx, hy);
    __nv_bfloat162 lo2 = __nv_bfloat162(lx, ly);
    lo_pack = *(unsigned*)&lo2;
    return *(unsigned*)&hi2;
}

// ---------------- split-convert x and W to bf16 hi/lo ----------------
#define NX4 (NN * CIN / 4)
#define WX4 (COUT * CIN / 4)
__global__ __launch_bounds__(256)
void k_conv(const float* __restrict__ x, const float* __restrict__ W) {
    int i = blockIdx.x * 256 + threadIdx.x;
    if (i < NX4) {
        float4 v = ((const float4*)x)[i];
        unsigned l0, l1;
        unsigned h0 = pack_split(v.x, v.y, l0);
        unsigned h1 = pack_split(v.z, v.w, l1);
        ((uint2*)g_xhi)[i] = make_uint2(h0, h1);
        ((uint2*)g_xlo)[i] = make_uint2(l0, l1);
    } else if (i < NX4 + WX4) {
        int j = i - NX4;
        float4 v = ((const float4*)W)[j];
        unsigned l0, l1;
        unsigned h0 = pack_split(v.x, v.y, l0);
        unsigned h1 = pack_split(v.z, v.w, l1);
        ((uint2*)g_whi)[j] = make_uint2(h0, h1);
        ((uint2*)g_wlo)[j] = make_uint2(l0, l1);
    }
}

// ---------------- clear bitmap + degree, fused dtype detection ----------------
__global__ void k_clear(const unsigned* __restrict__ e) {
    size_t i = (size_t)blockIdx.x * blockDim.x + threadIdx.x;
    if (i < BM_WORDS / 4) ((uint4*)g_bitmap)[i] = make_uint4(0u, 0u, 0u, 0u);
    if (i < NN) g_deg[i] = 0;
    if (blockIdx.x == 0) {
        unsigned v = (threadIdx.x < 128) ? e[threadIdx.x * 2 + 1] : 0u;
        int any = __syncthreads_or(v != 0u);
        if (threadIdx.x == 0) g_is64 = !any;
    }
}

__device__ __forceinline__ void edge_rc(const void* eidx, int is64, int i, int& r, int& c) {
    if (i < NE) {
        if (is64) {
            r = (int)((const long long*)eidx)[i];
            c = (int)((const long long*)eidx)[NE + i];
        } else {
            r = ((const int*)eidx)[i];
            c = ((const int*)eidx)[NE + i];
        }
    } else {
        r = c = i - NE;   // self loop
    }
}

// ---------------- mark distinct edges (1/thread for max atomic MLP) ----------------
__global__ __launch_bounds__(256)
void k_mark(const void* __restrict__ eidx) {
    int i = blockIdx.x * 256 + threadIdx.x;
    if (i >= NITEMS) return;
    int is64 = g_is64;
    int r, c;
    edge_rc(eidx, is64, i, r, c);
    size_t idx = (size_t)r * NN + c;
    unsigned bit = 1u << (idx & 31);
    unsigned old = atomicOr(&g_bitmap[idx >> 5], bit);
    g_rc[i] = (unsigned)r | ((unsigned)c << 16);
    unsigned short rk = 0xFFFFu;
    if (!(old & bit)) rk = (unsigned short)atomicAdd(&g_deg[r], 1);
    g_rank[i] = rk;
}

// ---------------- exclusive scan of degrees -> CSR offsets, dinv ----------------
__global__ void k_scan() {
    __shared__ int wsum[32];
    int t = threadIdx.x;
    int lane = t & 31, wid = t >> 5;
    int v[8];
    int s = 0;
    #pragma unroll
    for (int i = 0; i < 8; i++) { v[i] = g_deg[t * 8 + i]; s += v[i]; }
    int x = s;
    #pragma unroll
    for (int off = 1; off < 32; off <<= 1) {
        int y = __shfl_up_sync(0xffffffffu, x, off);
        if (lane >= off) x += y;
    }
    if (lane == 31) wsum[wid] = x;
    __syncthreads();
    if (wid == 0) {
        int y = wsum[lane];
        #pragma unroll
        for (int off = 1; off < 32; off <<= 1) {
            int z = __shfl_up_sync(0xffffffffu, y, off);
            if (lane >= off) y += z;
        }
        wsum[lane] = y;
    }
    __syncthreads();
    int excl = (wid ? wsum[wid - 1] : 0) + x - s;
    #pragma unroll
    for (int i = 0; i < 8; i++) {
        int n = t * 8 + i;
        g_off[n]  = excl;
        g_dinv[n] = rsqrtf((float)v[i]);
        excl += v[i];
    }
    if (t == 1023) g_off[NN] = wsum[31];
}

// ---------------- fill CSR columns (no atomics, 1 item/thread) ----------------
__global__ __launch_bounds__(256)
void k_fill() {
    int i = blockIdx.x * 256 + threadIdx.x;
    if (i >= NITEMS) return;
    unsigned short rk = g_rank[i];
    if (rk == 0xFFFFu) return;
    unsigned u = g_rc[i];
    g_cols[g_off[u & 0xFFFFu] + rk] = (int)(u >> 16);
}

// ---------------- tensor GEMM: h = x W^T + b via bf16 3-term split ----------------
// mma.sync m16n8k16. Block 128x128, BK=32, 256 thr = 8 warps, warp tile 64x32.
// cp.async 2-stage double buffer of pre-split bf16 operands; ldmatrix.x4
// fragment loads (pad-40 stride -> conflict-free).
#define BKP 40                     // smem row stride in bf16
#define ARR_B   (128 * BKP * 2)    // 10240 bytes per array
#define STAGE_B (4 * ARR_B)        // 40960 bytes per stage
#define GEMM_SMEM (2 * STAGE_B)    // 81920

__device__ __forceinline__ void mma_bf16(float* c, const unsigned* a, const unsigned* b) {
    asm volatile(
        "mma.sync.aligned.m16n8k16.row.col.f32.bf16.bf16.f32 "
        "{%0,%1,%2,%3}, {%4,%5,%6,%7}, {%8,%9}, {%0,%1,%2,%3};"
        : "+f"(c[0]), "+f"(c[1]), "+f"(c[2]), "+f"(c[3])
        : "r"(a[0]), "r"(a[1]), "r"(a[2]), "r"(a[3]), "r"(b[0]), "r"(b[1]));
}
__device__ __forceinline__ void ldsm4(unsigned* r, unsigned addr) {
    asm volatile("ldmatrix.sync.aligned.m8n8.x4.shared.b16 {%0,%1,%2,%3}, [%4];"
        : "=r"(r[0]), "=r"(r[1]), "=r"(r[2]), "=r"(r[3]) : "r"(addr));
}
__device__ __forceinline__ void cp16(unsigned saddr, const void* g) {
    asm volatile("cp.async.cg.shared.global [%0], [%1], 16;" :: "r"(saddr), "l"(g));
}

// issue one stage's 4 tiles: per thread 8 x 16B cp.async
__device__ __forceinline__ void gemm_issue(
    const __nv_bfloat16* xhi, const __nv_bfloat16* xlo,
    const __nv_bfloat16* whi, const __nv_bfloat16* wlo,
    int m0, int n0, int kt, unsigned sbase, int tid)
{
    int rlo = tid >> 2;        // 0..63
    int u   = tid & 3;         // 16B chunk within row
    const __nv_bfloat16* gsrc[4] = { xhi, xlo, whi, wlo };
    int base[4] = { m0, m0, n0, n0 };
    #pragma unroll
    for (int i = 0; i < 8; i++) {
        int arr = i >> 1;
        int row = (i & 1) * 64 + rlo;
        const __nv_bfloat16* g = gsrc[arr] + (size_t)(base[arr] + row) * CIN + kt + u * 8;
        unsigned s = sbase + arr * ARR_B + row * (BKP * 2) + u * 16;
        cp16(s, g);
    }
    asm volatile("cp.async.commit_group;" ::: "memory");
}

__global__ __launch_bounds__(256)
void k_gemm_tc(const __nv_bfloat16* __restrict__ xhi, const __nv_bfloat16* __restrict__ xlo,
               const __nv_bfloat16* __restrict__ whi, const __nv_bfloat16* __restrict__ wlo,
               const float* __restrict__ bias, float* __restrict__ C) {
    extern __shared__ char smem[];
    unsigned sb = (unsigned)__cvta_generic_to_shared(smem);

    int tid = threadIdx.x;
    int m0 = blockIdx.y * 128;
    int n0 = blockIdx.x * 128;
    int lane = tid & 31, w = tid >> 5;
    int wm = (w & 1) * 64;       // warp row offset
    int wn = (w >> 1) * 32;      // warp col offset
    int g  = lane >> 2;          // 0..7
    int tg = lane & 3;           // 0..3

    // ldmatrix per-lane address components (verified layout, R5)
    int jj = lane >> 3, jr = lane & 7;
    unsigned aoff = (unsigned)(((wm + (jj & 1) * 8 + jr) * BKP + (jj >> 1) * 8) * 2);
    unsigned boff = (unsigned)(((wn + (jj >> 1) * 8 + jr) * BKP + (jj & 1) * 8) * 2);

    float acc[4][4][4];
    #pragma unroll
    for (int mi = 0; mi < 4; mi++)
        #pragma unroll
        for (int ni = 0; ni < 4; ni++)
            #pragma unroll
            for (int q = 0; q < 4; q++) acc[mi][ni][q] = 0.f;

    // prologue: stages 0 and 1 in flight
    gemm_issue(xhi, xlo, whi, wlo, m0, n0, 0,  sb,           tid);
    gemm_issue(xhi, xlo, whi, wlo, m0, n0, 32, sb + STAGE_B, tid);

    #pragma unroll 1
    for (int ch = 0; ch < 16; ch++) {
        if (ch < 15) asm volatile("cp.async.wait_group 1;" ::: "memory");
        else         asm volatile("cp.async.wait_group 0;" ::: "memory");
        __syncthreads();

        unsigned sbase = sb + (unsigned)((ch & 1) * STAGE_B);
        unsigned a1addr = sbase + aoff;
        unsigned a2addr = sbase + ARR_B + aoff;
        unsigned b1addr = sbase + 2 * ARR_B + boff;
        unsigned b2addr = sbase + 3 * ARR_B + boff;

        #pragma unroll
        for (int ks = 0; ks < 2; ks++) {
            unsigned kb = (unsigned)(ks * 16 * 2);
            unsigned af[4][4], bf[2][4], bg[2][4];
            #pragma unroll
            for (int mi = 0; mi < 4; mi++)
                ldsm4(af[mi], a1addr + (unsigned)(mi * 16 * BKP * 2) + kb);
            #pragma unroll
            for (int p = 0; p < 2; p++)
                ldsm4(bf[p], b1addr + (unsigned)(p * 16 * BKP * 2) + kb);
            #pragma unroll
            for (int mi = 0; mi < 4; mi++)
                #pragma unroll
                for (int ni = 0; ni < 4; ni++)
                    mma_bf16(acc[mi][ni], af[mi], &bf[ni >> 1][(ni & 1) * 2]);  // hi*hi
            #pragma unroll
            for (int p = 0; p < 2; p++)
                ldsm4(bg[p], b2addr + (unsigned)(p * 16 * BKP * 2) + kb);
            #pragma unroll
            for (int mi = 0; mi < 4; mi++)
                #pragma unroll
                for (int ni = 0; ni < 4; ni++)
                    mma_bf16(acc[mi][ni], af[mi], &bg[ni >> 1][(ni & 1) * 2]);  // hi*lo
            #pragma unroll
            for (int mi = 0; mi < 4; mi++)
                ldsm4(af[mi], a2addr + (unsigned)(mi * 16 * BKP * 2) + kb);
            #pragma unroll
            for (int mi = 0; mi < 4; mi++)
                #pragma unroll
                for (int ni = 0; ni < 4; ni++)
                    mma_bf16(acc[mi][ni], af[mi], &bf[ni >> 1][(ni & 1) * 2]);  // lo*hi
        }
        __syncthreads();   // everyone done reading this buffer
        if (ch + 2 < 16)
            gemm_issue(xhi, xlo, whi, wlo, m0, n0, (ch + 2) * 32,
                       sb + (unsigned)((ch & 1) * STAGE_B), tid);
    }

    // epilogue: add bias, write fp32 (verified layout, R5)
    #pragma unroll
    for (int mi = 0; mi < 4; mi++) {
        int r0 = m0 + wm + mi * 16 + g;
        #pragma unroll
        for (int ni = 0; ni < 4; ni++) {
            int col = n0 + wn + ni * 8 + tg * 2;
            float b0 = bias[col], b1 = bias[col + 1];
            float* p0 = C + (size_t)r0 * COUT + col;
            float* p1 = C + (size_t)(r0 + 8) * COUT + col;
            p0[0] = acc[mi][ni][0] + b0;
            p0[1] = acc[mi][ni][1] + b1;
            p1[0] = acc[mi][ni][2] + b0;
            p1[1] = acc[mi][ni][3] + b1;
        }
    }
}

// ---------------- aggregation: out[r] = dinv[r] * sum_{c in N(r)} dinv[c] * h[c] ----------------
__global__ __launch_bounds__(128)
void k_agg(const float* __restrict__ h, float* __restrict__ out) {
    __shared__ int   sc[256];
    __shared__ float sd[256];
    int r = blockIdx.x;
    int t = threadIdx.x;
    int beg = g_off[r], end = g_off[r + 1];
    float4 acc = make_float4(0.f, 0.f, 0.f, 0.f);

    for (int base = beg; base < end; base += 256) {
        int cnt = min(256, end - base);
        for (int j = t; j < cnt; j += 128) {
            int c = g_cols[base + j];
            sc[j] = c;
            sd[j] = g_dinv[c];
        }
        __syncthreads();
        #pragma unroll 4
        for (int j = 0; j < cnt; j++) {
            const float4* hv = (const float4*)(h + (size_t)sc[j] * COUT);
            float s = sd[j];
            float4 v = hv[t];
            acc.x = fmaf(s, v.x, acc.x);
            acc.y = fmaf(s, v.y, acc.y);
            acc.z = fmaf(s, v.z, acc.z);
            acc.w = fmaf(s, v.w, acc.w);
        }
        __syncthreads();
    }

    float dr = g_dinv[r];
    ((float4*)(out + (size_t)r * COUT))[t] =
        make_float4(dr * acc.x, dr * acc.y, dr * acc.z, dr * acc.w);
}

// ---------------- launch ----------------
extern "C" void kernel_launch(void* const* d_in, const int* in_sizes, int n_in,
                              void* d_out, int out_size) {
    const float* x    = (const float*)d_in[0];
    const void*  eidx = d_in[1];
    const float* W    = (const float*)d_in[2];
    const float* b    = (const float*)d_in[3];
    float* out = (float*)d_out;

    float* h_ptr;
    cudaGetSymbolAddress((void**)&h_ptr, g_h);
    __nv_bfloat16 *xhi, *xlo, *whi, *wlo;
    cudaGetSymbolAddress((void**)&xhi, g_xhi);
    cudaGetSymbolAddress((void**)&xlo, g_xlo);
    cudaGetSymbolAddress((void**)&whi, g_whi);
    cudaGetSymbolAddress((void**)&wlo, g_wlo);

    cudaFuncSetAttribute(k_gemm_tc, cudaFuncAttributeMaxDynamicSharedMemorySize, GEMM_SMEM);

    // 1. split-convert x, W to bf16 hi/lo
    k_conv<<<(NX4 + WX4 + 255) / 256, 256>>>(x, W);
    // 2. clear bitmap + degrees (+ dtype detect in block 0)
    k_clear<<<(int)(BM_WORDS / 4 / 256), 256>>>((const unsigned*)eidx);
    // 3. mark distinct edges + degree + rank + packed rc (1/thread)
    k_mark<<<(NITEMS + 255) / 256, 256>>>(eidx);
    // 4. scan -> CSR offsets, dinv
    k_scan<<<1, 1024>>>();
    // 5. fill CSR cols (no atomics, 1 item/thread)
    k_fill<<<(NITEMS + 255) / 256, 256>>>();
    // 6. h = x W^T + b (tensor cores, cp.async pipeline)
    {
        dim3 grid(COUT / 128, NN / 128);  // (4, 64)
        k_gemm_tc<<<grid, 256, GEMM_SMEM>>>(xhi, xlo, whi, wlo, b, h_ptr);
    }
    // 7. aggregate
    k_agg<<<NN, 128>>>(h_ptr, out);
}

// round 9
// speedup vs baseline: 1.5334x; 1.5095x over previous
#include <cuda_runtime.h>
#include <cuda_bf16.h>
#include <stdint.h>

// Problem constants (fixed shapes)
#define NN      8192        // nodes
#define NE      262144      // edges
#define CIN     512
#define COUT    512
#define NITEMS  (NE + NN)   // 270336 = 264*1024
#define BM_WORDS ((size_t)NN * NN / 32)   // 8 MB bitmap
#define SCAN_BLKS 32        // 8192 / 256

// ---------------- device scratch (no allocations allowed) ----------------
__device__ unsigned g_bitmap[BM_WORDS];
__device__ int      g_deg[NN];
__device__ int      g_off[NN + 1];
__device__ float    g_dinv[NN];
__device__ int      g_cols[NITEMS];
__device__ unsigned short g_rank[NITEMS];    // slot within row; 0xFFFF = duplicate
__device__ unsigned g_rc[NITEMS];            // packed r | c<<16
__device__ int      g_bsum[SCAN_BLKS];
__device__ int      g_boff[SCAN_BLKS];
__device__ float    g_h[(size_t)NN * COUT];  // 16 MB: h = xW^T + b
__device__ int      g_is64;

// ---------------- clear bitmap + degree, fused dtype detection ----------------
__global__ void k_clear(const unsigned* __restrict__ e) {
    size_t i = (size_t)blockIdx.x * blockDim.x + threadIdx.x;
    if (i < BM_WORDS / 4) ((uint4*)g_bitmap)[i] = make_uint4(0u, 0u, 0u, 0u);
    if (i < NN) g_deg[i] = 0;
    if (blockIdx.x == 0) {
        unsigned v = (threadIdx.x < 128) ? e[threadIdx.x * 2 + 1] : 0u;
        int any = __syncthreads_or(v != 0u);
        if (threadIdx.x == 0) g_is64 = !any;
    }
}

__device__ __forceinline__ void edge_rc(const void* eidx, int is64, int i, int& r, int& c) {
    if (i < NE) {
        if (is64) {
            r = (int)((const long long*)eidx)[i];
            c = (int)((const long long*)eidx)[NE + i];
        } else {
            r = ((const int*)eidx)[i];
            c = ((const int*)eidx)[NE + i];
        }
    } else {
        r = c = i - NE;   // self loop
    }
}

// ---------------- mark distinct edges (1/thread; rank = slot within row) ----------------
__global__ __launch_bounds__(256)
void k_mark(const void* __restrict__ eidx) {
    int i = blockIdx.x * 256 + threadIdx.x;
    if (i >= NITEMS) return;
    int is64 = g_is64;
    int r, c;
    edge_rc(eidx, is64, i, r, c);
    size_t idx = (size_t)r * NN + c;
    unsigned bit = 1u << (idx & 31);
    unsigned old = atomicOr(&g_bitmap[idx >> 5], bit);
    g_rc[i] = (unsigned)r | ((unsigned)c << 16);
    unsigned short rk = 0xFFFFu;
    if (!(old & bit)) rk = (unsigned short)atomicAdd(&g_deg[r], 1);
    g_rank[i] = rk;
}

// ---------------- 3-phase multi-block scan (avoids grid=1 pathology) ----------------
// Phase A: 32 blocks x 256 -> per-block degree sums
__global__ __launch_bounds__(256)
void k_scan_a() {
    __shared__ int ws[8];
    int i = blockIdx.x * 256 + threadIdx.x;
    int lane = threadIdx.x & 31, wid = threadIdx.x >> 5;
    int s = g_deg[i];
    #pragma unroll
    for (int off = 16; off > 0; off >>= 1) s += __shfl_down_sync(0xffffffffu, s, off);
    if (lane == 0) ws[wid] = s;
    __syncthreads();
    if (threadIdx.x == 0) {
        int t = 0;
        #pragma unroll
        for (int k = 0; k < 8; k++) t += ws[k];
        g_bsum[blockIdx.x] = t;
    }
}
// Phase B: one warp scans the 32 block sums -> exclusive block offsets
__global__ void k_scan_b() {
    int t = threadIdx.x;
    int v = g_bsum[t];
    int x = v;
    #pragma unroll
    for (int off = 1; off < 32; off <<= 1) {
        int y = __shfl_up_sync(0xffffffffu, x, off);
        if (t >= off) x += y;
    }
    g_boff[t] = x - v;
    if (t == 31) g_off[NN] = x;
}
// Phase C: 32 blocks x 256, block-local exclusive scan + block offset
__global__ __launch_bounds__(256)
void k_scan_c() {
    __shared__ int ws[8];
    int i = blockIdx.x * 256 + threadIdx.x;
    int lane = threadIdx.x & 31, wid = threadIdx.x >> 5;
    int v = g_deg[i];
    int x = v;
    #pragma unroll
    for (int off = 1; off < 32; off <<= 1) {
        int y = __shfl_up_sync(0xffffffffu, x, off);
        if (lane >= off) x += y;
    }
    if (lane == 31) ws[wid] = x;
    __syncthreads();
    if (wid == 0 && lane < 8) {
        int y = ws[lane];
        #pragma unroll
        for (int off = 1; off < 8; off <<= 1) {
            int z = __shfl_up_sync(0xffu, y, off);
            if (lane >= off) y += z;
        }
        ws[lane] = y;
    }
    __syncthreads();
    int base = (wid ? ws[wid - 1] : 0) + g_boff[blockIdx.x];
    g_off[i]  = base + x - v;
    g_dinv[i] = rsqrtf((float)v);   // deg >= 1 (self loop)
}

// ---------------- fill CSR columns (no atomics, no edge re-read) ----------------
__global__ __launch_bounds__(256)
void k_fill() {
    int i = blockIdx.x * 256 + threadIdx.x;
    if (i >= NITEMS) return;
    unsigned short rk = g_rank[i];
    if (rk == 0xFFFFu) return;
    unsigned u = g_rc[i];
    g_cols[g_off[u & 0xFFFFu] + rk] = (int)(u >> 16);
}

// ---------------- tensor GEMM: h = x W^T + b via bf16 3-term split ----------------
// (R3 version verbatim — proven 48us / rel_err 4.8e-6 at total 121.3)
#define BKP 40   // smem row stride in bf16 elems (conflict-free for k-pair loads)

__device__ __forceinline__ void mma_bf16(float* c, const unsigned* a, const unsigned* b) {
    asm volatile(
        "mma.sync.aligned.m16n8k16.row.col.f32.bf16.bf16.f32 "
        "{%0,%1,%2,%3}, {%4,%5,%6,%7}, {%8,%9}, {%0,%1,%2,%3};"
        : "+f"(c[0]), "+f"(c[1]), "+f"(c[2]), "+f"(c[3])
        : "r"(a[0]), "r"(a[1]), "r"(a[2]), "r"(a[3]), "r"(b[0]), "r"(b[1]));
}

__device__ __forceinline__ unsigned pack_split(float x, float y, unsigned& lo_pack) {
    __nv_bfloat16 hx = __float2bfloat16(x);
    __nv_bfloat16 hy = __float2bfloat16(y);
    __nv_bfloat16 lx = __float2bfloat16(x - __bfloat162float(hx));
    __nv_bfloat16 ly = __float2bfloat16(y - __bfloat162float(hy));
    __nv_bfloat162 hi2 = __nv_bfloat162(hx, hy);
    __nv_bfloat162 lo2 = __nv_bfloat162(lx, ly);
    lo_pack = *(unsigned*)&lo2;
    return *(unsigned*)&hi2;
}

__global__ __launch_bounds__(256)
void k_gemm_tc(const float* __restrict__ A, const float* __restrict__ W,
               const float* __restrict__ bias, float* __restrict__ C) {
    __shared__ __nv_bfloat16 sA1[128 * BKP];
    __shared__ __nv_bfloat16 sA2[128 * BKP];
    __shared__ __nv_bfloat16 sB1[128 * BKP];
    __shared__ __nv_bfloat16 sB2[128 * BKP];

    int tid = threadIdx.x;
    int m0 = blockIdx.y * 128;
    int n0 = blockIdx.x * 128;
    int lane = tid & 31, w = tid >> 5;
    int wm = (w & 1) * 64;       // warp row offset
    int wn = (w >> 1) * 32;      // warp col offset
    int g  = lane >> 2;          // 0..7
    int tg = lane & 3;           // 0..3

    float acc[4][4][4];
    #pragma unroll
    for (int mi = 0; mi < 4; mi++)
        #pragma unroll
        for (int ni = 0; ni < 4; ni++)
            #pragma unroll
            for (int q = 0; q < 4; q++) acc[mi][ni][q] = 0.f;

    int lr = tid >> 3;          // 0..31 (row within 32-row group)
    int lc = (tid & 7) * 4;     // k offset 0..28

    #pragma unroll 1
    for (int kt = 0; kt < CIN; kt += 32) {
        #pragma unroll
        for (int rr = 0; rr < 4; rr++) {
            int r = lr + rr * 32;
            float4 va = *(const float4*)(A + (size_t)(m0 + r) * CIN + kt + lc);
            float4 vb = *(const float4*)(W + (size_t)(n0 + r) * CIN + kt + lc);
            unsigned lo;
            unsigned hi;
            hi = pack_split(va.x, va.y, lo);
            *(unsigned*)&sA1[r * BKP + lc]     = hi; *(unsigned*)&sA2[r * BKP + lc]     = lo;
            hi = pack_split(va.z, va.w, lo);
            *(unsigned*)&sA1[r * BKP + lc + 2] = hi; *(unsigned*)&sA2[r * BKP + lc + 2] = lo;
            hi = pack_split(vb.x, vb.y, lo);
            *(unsigned*)&sB1[r * BKP + lc]     = hi; *(unsigned*)&sB2[r * BKP + lc]     = lo;
            hi = pack_split(vb.z, vb.w, lo);
            *(unsigned*)&sB1[r * BKP + lc + 2] = hi; *(unsigned*)&sB2[r * BKP + lc + 2] = lo;
        }
        __syncthreads();

        #pragma unroll
        for (int ks = 0; ks < 2; ks++) {
            int k0 = ks * 16 + tg * 2;
            unsigned a1f[4][4], a2f[4][4];
            #pragma unroll
            for (int mi = 0; mi < 4; mi++) {
                int r0 = wm + mi * 16 + g;
                a1f[mi][0] = *(unsigned*)&sA1[r0 * BKP + k0];
                a1f[mi][1] = *(unsigned*)&sA1[(r0 + 8) * BKP + k0];
                a1f[mi][2] = *(unsigned*)&sA1[r0 * BKP + k0 + 8];
                a1f[mi][3] = *(unsigned*)&sA1[(r0 + 8) * BKP + k0 + 8];
                a2f[mi][0] = *(unsigned*)&sA2[r0 * BKP + k0];
                a2f[mi][1] = *(unsigned*)&sA2[(r0 + 8) * BKP + k0];
                a2f[mi][2] = *(unsigned*)&sA2[r0 * BKP + k0 + 8];
                a2f[mi][3] = *(unsigned*)&sA2[(r0 + 8) * BKP + k0 + 8];
            }
            unsigned b1f[4][2], b2f[4][2];
            #pragma unroll
            for (int ni = 0; ni < 4; ni++) {
                int c = wn + ni * 8 + g;
                b1f[ni][0] = *(unsigned*)&sB1[c * BKP + k0];
                b1f[ni][1] = *(unsigned*)&sB1[c * BKP + k0 + 8];
                b2f[ni][0] = *(unsigned*)&sB2[c * BKP + k0];
                b2f[ni][1] = *(unsigned*)&sB2[c * BKP + k0 + 8];
            }
            #pragma unroll
            for (int mi = 0; mi < 4; mi++)
                #pragma unroll
                for (int ni = 0; ni < 4; ni++) {
                    mma_bf16(acc[mi][ni], a1f[mi], b1f[ni]);  // hi*hi
                    mma_bf16(acc[mi][ni], a1f[mi], b2f[ni]);  // hi*lo
                    mma_bf16(acc[mi][ni], a2f[mi], b1f[ni]);  // lo*hi
                }
        }
        __syncthreads();
    }

    // epilogue: add bias, write fp32
    #pragma unroll
    for (int mi = 0; mi < 4; mi++) {
        int r0 = m0 + wm + mi * 16 + g;
        #pragma unroll
        for (int ni = 0; ni < 4; ni++) {
            int col = n0 + wn + ni * 8 + tg * 2;
            float b0 = bias[col], b1 = bias[col + 1];
            float* p0 = C + (size_t)r0 * COUT + col;
            float* p1 = C + (size_t)(r0 + 8) * COUT + col;
            p0[0] = acc[mi][ni][0] + b0;
            p0[1] = acc[mi][ni][1] + b1;
            p1[0] = acc[mi][ni][2] + b0;
            p1[1] = acc[mi][ni][3] + b1;
        }
    }
}

// ---------------- aggregation: out[r] = dinv[r] * sum_{c in N(r)} dinv[c] * h[c] ----------------
__global__ __launch_bounds__(128)
void k_agg(const float* __restrict__ h, float* __restrict__ out) {
    __shared__ int   sc[256];
    __shared__ float sd[256];
    int r = blockIdx.x;
    int t = threadIdx.x;
    int beg = g_off[r], end = g_off[r + 1];
    float4 acc = make_float4(0.f, 0.f, 0.f, 0.f);

    for (int base = beg; base < end; base += 256) {
        int cnt = min(256, end - base);
        for (int j = t; j < cnt; j += 128) {
            int c = g_cols[base + j];
            sc[j] = c;
            sd[j] = g_dinv[c];
        }
        __syncthreads();
        #pragma unroll 4
        for (int j = 0; j < cnt; j++) {
            const float4* hv = (const float4*)(h + (size_t)sc[j] * COUT);
            float s = sd[j];
            float4 v = hv[t];
            acc.x = fmaf(s, v.x, acc.x);
            acc.y = fmaf(s, v.y, acc.y);
            acc.z = fmaf(s, v.z, acc.z);
            acc.w = fmaf(s, v.w, acc.w);
        }
        __syncthreads();
    }

    float dr = g_dinv[r];
    ((float4*)(out + (size_t)r * COUT))[t] =
        make_float4(dr * acc.x, dr * acc.y, dr * acc.z, dr * acc.w);
}

// ---------------- launch ----------------
extern "C" void kernel_launch(void* const* d_in, const int* in_sizes, int n_in,
                              void* d_out, int out_size) {
    const float* x    = (const float*)d_in[0];
    const void*  eidx = d_in[1];
    const float* W    = (const float*)d_in[2];
    const float* b    = (const float*)d_in[3];
    float* out = (float*)d_out;

    float* h_ptr;
    cudaGetSymbolAddress((void**)&h_ptr, g_h);

    // 1. clear bitmap + degrees (+ dtype detect in block 0)
    k_clear<<<(int)(BM_WORDS / 4 / 256), 256>>>((const unsigned*)eidx);
    // 2. mark distinct edges + degree + rank + packed rc (1/thread)
    k_mark<<<(NITEMS + 255) / 256, 256>>>(eidx);
    // 3. scan -> CSR offsets, dinv (3-phase, multi-block)
    k_scan_a<<<SCAN_BLKS, 256>>>();
    k_scan_b<<<1, 32>>>();
    k_scan_c<<<SCAN_BLKS, 256>>>();
    // 4. fill CSR cols (no atomics, 1 item/thread)
    k_fill<<<(NITEMS + 255) / 256, 256>>>();
    // 5. h = x W^T + b (tensor cores)
    {
        dim3 grid(COUT / 128, NN / 128);  // (4, 64)
        k_gemm_tc<<<grid, 256>>>(x, W, b, h_ptr);
    }
    // 6. aggregate
    k_agg<<<NN, 128>>>(h_ptr, out);
}

// round 10
// speedup vs baseline: 1.7324x; 1.1298x over previous
#include <cuda_runtime.h>
#include <cuda_bf16.h>
#include <cuda_fp16.h>
#include <stdint.h>

// Problem constants (fixed shapes)
#define NN      8192        // nodes
#define NE      262144      // edges
#define CIN     512
#define COUT    512
#define NITEMS  (NE + NN)   // 270336 = 264*1024
#define BM_WORDS ((size_t)NN * NN / 32)   // 8 MB bitmap
#define SCAN_BLKS 32        // 8192 / 256

// ---------------- device scratch (no allocations allowed) ----------------
__device__ unsigned g_bitmap[BM_WORDS];
__device__ int      g_deg[NN];
__device__ int      g_off[NN + 1];
__device__ float    g_dinv[NN];
__device__ int      g_cols[NITEMS];
__device__ unsigned short g_rank[NITEMS];    // slot within row; 0xFFFF = duplicate
__device__ unsigned g_rc[NITEMS];            // packed r | c<<16
__device__ int      g_bsum[SCAN_BLKS];
__device__ __half   g_h[(size_t)NN * COUT];  // 8 MB: h = xW^T + b (fp16)
__device__ int      g_is64;

// ---------------- clear bitmap + degree, fused dtype detection ----------------
__global__ void k_clear(const unsigned* __restrict__ e) {
    size_t i = (size_t)blockIdx.x * blockDim.x + threadIdx.x;
    if (i < BM_WORDS / 4) ((uint4*)g_bitmap)[i] = make_uint4(0u, 0u, 0u, 0u);
    if (i < NN) g_deg[i] = 0;
    if (blockIdx.x == 0) {
        unsigned v = (threadIdx.x < 128) ? e[threadIdx.x * 2 + 1] : 0u;
        int any = __syncthreads_or(v != 0u);
        if (threadIdx.x == 0) g_is64 = !any;
    }
}

__device__ __forceinline__ void edge_rc(const void* eidx, int is64, int i, int& r, int& c) {
    if (i < NE) {
        if (is64) {
            r = (int)((const long long*)eidx)[i];
            c = (int)((const long long*)eidx)[NE + i];
        } else {
            r = ((const int*)eidx)[i];
            c = ((const int*)eidx)[NE + i];
        }
    } else {
        r = c = i - NE;   // self loop
    }
}

// ---------------- mark distinct edges (1/thread; rank = slot within row) ----------------
__global__ __launch_bounds__(256)
void k_mark(const void* __restrict__ eidx) {
    int i = blockIdx.x * 256 + threadIdx.x;
    if (i >= NITEMS) return;
    int is64 = g_is64;
    int r, c;
    edge_rc(eidx, is64, i, r, c);
    size_t idx = (size_t)r * NN + c;
    unsigned bit = 1u << (idx & 31);
    unsigned old = atomicOr(&g_bitmap[idx >> 5], bit);
    g_rc[i] = (unsigned)r | ((unsigned)c << 16);
    unsigned short rk = 0xFFFFu;
    if (!(old & bit)) rk = (unsigned short)atomicAdd(&g_deg[r], 1);
    g_rank[i] = rk;
}

// ---------------- 2-phase multi-block scan ----------------
// Phase A: 32 blocks x 256 -> per-block degree sums
__global__ __launch_bounds__(256)
void k_scan_a() {
    __shared__ int ws[8];
    int i = blockIdx.x * 256 + threadIdx.x;
    int lane = threadIdx.x & 31, wid = threadIdx.x >> 5;
    int s = g_deg[i];
    #pragma unroll
    for (int off = 16; off > 0; off >>= 1) s += __shfl_down_sync(0xffffffffu, s, off);
    if (lane == 0) ws[wid] = s;
    __syncthreads();
    if (threadIdx.x == 0) {
        int t = 0;
        #pragma unroll
        for (int k = 0; k < 8; k++) t += ws[k];
        g_bsum[blockIdx.x] = t;
    }
}
// Phase C: 32 blocks x 256; warp 1 re-scans the 32 block sums locally (no
// separate grid=1 kernel), block-local exclusive scan + block offset.
__global__ __launch_bounds__(256)
void k_scan_c() {
    __shared__ int ws[8];
    __shared__ int sb32[32];
    int i = blockIdx.x * 256 + threadIdx.x;
    int lane = threadIdx.x & 31, wid = threadIdx.x >> 5;
    int v = g_deg[i];
    int x = v;
    #pragma unroll
    for (int off = 1; off < 32; off <<= 1) {
        int y = __shfl_up_sync(0xffffffffu, x, off);
        if (lane >= off) x += y;
    }
    if (lane == 31) ws[wid] = x;
    if (wid == 1) {   // warp 1 also scans the 32 global block sums
        int b = g_bsum[lane];
        int xx = b;
        #pragma unroll
        for (int off = 1; off < 32; off <<= 1) {
            int y = __shfl_up_sync(0xffffffffu, xx, off);
            if (lane >= off) xx += y;
        }
        sb32[lane] = xx;
        if (blockIdx.x == SCAN_BLKS - 1 && lane == 31) g_off[NN] = xx;
    }
    __syncthreads();
    if (wid == 0 && lane < 8) {
        int y = ws[lane];
        #pragma unroll
        for (int off = 1; off < 8; off <<= 1) {
            int z = __shfl_up_sync(0xffu, y, off);
            if (lane >= off) y += z;
        }
        ws[lane] = y;
    }
    __syncthreads();
    int boff = blockIdx.x ? sb32[blockIdx.x - 1] : 0;
    int base = (wid ? ws[wid - 1] : 0) + boff;
    g_off[i]  = base + x - v;
    g_dinv[i] = rsqrtf((float)v);   // deg >= 1 (self loop)
}

// ---------------- fill CSR columns (no atomics, no edge re-read) ----------------
__global__ __launch_bounds__(256)
void k_fill() {
    int i = blockIdx.x * 256 + threadIdx.x;
    if (i >= NITEMS) return;
    unsigned short rk = g_rank[i];
    if (rk == 0xFFFFu) return;
    unsigned u = g_rc[i];
    g_cols[g_off[u & 0xFFFFu] + rk] = (int)(u >> 16);
}

// ---------------- tensor GEMM: h = x W^T + b via bf16 3-term split ----------------
// (R3 mainloop verbatim — measured at ~90% of the mma.sync bf16 pipe ceiling.
//  Only the epilogue changed: h is written as fp16.)
#define BKP 40   // smem row stride in bf16 elems (conflict-free for k-pair loads)

__device__ __forceinline__ void mma_bf16(float* c, const unsigned* a, const unsigned* b) {
    asm volatile(
        "mma.sync.aligned.m16n8k16.row.col.f32.bf16.bf16.f32 "
        "{%0,%1,%2,%3}, {%4,%5,%6,%7}, {%8,%9}, {%0,%1,%2,%3};"
        : "+f"(c[0]), "+f"(c[1]), "+f"(c[2]), "+f"(c[3])
        : "r"(a[0]), "r"(a[1]), "r"(a[2]), "r"(a[3]), "r"(b[0]), "r"(b[1]));
}

__device__ __forceinline__ unsigned pack_split(float x, float y, unsigned& lo_pack) {
    __nv_bfloat16 hx = __float2bfloat16(x);
    __nv_bfloat16 hy = __float2bfloat16(y);
    __nv_bfloat16 lx = __float2bfloat16(x - __bfloat162float(hx));
    __nv_bfloat16 ly = __float2bfloat16(y - __bfloat162float(hy));
    __nv_bfloat162 hi2 = __nv_bfloat162(hx, hy);
    __nv_bfloat162 lo2 = __nv_bfloat162(lx, ly);
    lo_pack = *(unsigned*)&lo2;
    return *(unsigned*)&hi2;
}

__global__ __launch_bounds__(256)
void k_gemm_tc(const float* __restrict__ A, const float* __restrict__ W,
               const float* __restrict__ bias, __half* __restrict__ C) {
    __shared__ __nv_bfloat16 sA1[128 * BKP];
    __shared__ __nv_bfloat16 sA2[128 * BKP];
    __shared__ __nv_bfloat16 sB1[128 * BKP];
    __shared__ __nv_bfloat16 sB2[128 * BKP];

    int tid = threadIdx.x;
    int m0 = blockIdx.y * 128;
    int n0 = blockIdx.x * 128;
    int lane = tid & 31, w = tid >> 5;
    int wm = (w & 1) * 64;       // warp row offset
    int wn = (w >> 1) * 32;      // warp col offset
    int g  = lane >> 2;          // 0..7
    int tg = lane & 3;           // 0..3

    float acc[4][4][4];
    #pragma unroll
    for (int mi = 0; mi < 4; mi++)
        #pragma unroll
        for (int ni = 0; ni < 4; ni++)
            #pragma unroll
            for (int q = 0; q < 4; q++) acc[mi][ni][q] = 0.f;

    int lr = tid >> 3;          // 0..31 (row within 32-row group)
    int lc = (tid & 7) * 4;     // k offset 0..28

    #pragma unroll 1
    for (int kt = 0; kt < CIN; kt += 32) {
        #pragma unroll
        for (int rr = 0; rr < 4; rr++) {
            int r = lr + rr * 32;
            float4 va = *(const float4*)(A + (size_t)(m0 + r) * CIN + kt + lc);
            float4 vb = *(const float4*)(W + (size_t)(n0 + r) * CIN + kt + lc);
            unsigned lo;
            unsigned hi;
            hi = pack_split(va.x, va.y, lo);
            *(unsigned*)&sA1[r * BKP + lc]     = hi; *(unsigned*)&sA2[r * BKP + lc]     = lo;
            hi = pack_split(va.z, va.w, lo);
            *(unsigned*)&sA1[r * BKP + lc + 2] = hi; *(unsigned*)&sA2[r * BKP + lc + 2] = lo;
            hi = pack_split(vb.x, vb.y, lo);
            *(unsigned*)&sB1[r * BKP + lc]     = hi; *(unsigned*)&sB2[r * BKP + lc]     = lo;
            hi = pack_split(vb.z, vb.w, lo);
            *(unsigned*)&sB1[r * BKP + lc + 2] = hi; *(unsigned*)&sB2[r * BKP + lc + 2] = lo;
        }
        __syncthreads();

        #pragma unroll
        for (int ks = 0; ks < 2; ks++) {
            int k0 = ks * 16 + tg * 2;
            unsigned a1f[4][4], a2f[4][4];
            #pragma unroll
            for (int mi = 0; mi < 4; mi++) {
                int r0 = wm + mi * 16 + g;
                a1f[mi][0] = *(unsigned*)&sA1[r0 * BKP + k0];
                a1f[mi][1] = *(unsigned*)&sA1[(r0 + 8) * BKP + k0];
                a1f[mi][2] = *(unsigned*)&sA1[r0 * BKP + k0 + 8];
                a1f[mi][3] = *(unsigned*)&sA1[(r0 + 8) * BKP + k0 + 8];
                a2f[mi][0] = *(unsigned*)&sA2[r0 * BKP + k0];
                a2f[mi][1] = *(unsigned*)&sA2[(r0 + 8) * BKP + k0];
                a2f[mi][2] = *(unsigned*)&sA2[r0 * BKP + k0 + 8];
                a2f[mi][3] = *(unsigned*)&sA2[(r0 + 8) * BKP + k0 + 8];
            }
            unsigned b1f[4][2], b2f[4][2];
            #pragma unroll
            for (int ni = 0; ni < 4; ni++) {
                int c = wn + ni * 8 + g;
                b1f[ni][0] = *(unsigned*)&sB1[c * BKP + k0];
                b1f[ni][1] = *(unsigned*)&sB1[c * BKP + k0 + 8];
                b2f[ni][0] = *(unsigned*)&sB2[c * BKP + k0];
                b2f[ni][1] = *(unsigned*)&sB2[c * BKP + k0 + 8];
            }
            #pragma unroll
            for (int mi = 0; mi < 4; mi++)
                #pragma unroll
                for (int ni = 0; ni < 4; ni++) {
                    mma_bf16(acc[mi][ni], a1f[mi], b1f[ni]);  // hi*hi
                    mma_bf16(acc[mi][ni], a1f[mi], b2f[ni]);  // hi*lo
                    mma_bf16(acc[mi][ni], a2f[mi], b1f[ni]);  // lo*hi
                }
        }
        __syncthreads();
    }

    // epilogue: add bias (fp32), write h as fp16
    #pragma unroll
    for (int mi = 0; mi < 4; mi++) {
        int r0 = m0 + wm + mi * 16 + g;
        #pragma unroll
        for (int ni = 0; ni < 4; ni++) {
            int col = n0 + wn + ni * 8 + tg * 2;
            float b0 = bias[col], b1 = bias[col + 1];
            __half* p0 = C + (size_t)r0 * COUT + col;
            __half* p1 = C + (size_t)(r0 + 8) * COUT + col;
            *(__half2*)p0 = __floats2half2_rn(acc[mi][ni][0] + b0, acc[mi][ni][1] + b1);
            *(__half2*)p1 = __floats2half2_rn(acc[mi][ni][2] + b0, acc[mi][ni][3] + b1);
        }
    }
}

// ---------------- aggregation: out[r] = dinv[r] * sum_{c in N(r)} dinv[c] * h[c] ----------------
// h gathered as fp16 (half the L2 traffic), fp32 accumulation.
__global__ __launch_bounds__(128)
void k_agg(const __half* __restrict__ h, float* __restrict__ out) {
    __shared__ int   sc[256];
    __shared__ float sd[256];
    int r = blockIdx.x;
    int t = threadIdx.x;
    int beg = g_off[r], end = g_off[r + 1];
    float4 acc = make_float4(0.f, 0.f, 0.f, 0.f);

    for (int base = beg; base < end; base += 256) {
        int cnt = min(256, end - base);
        for (int j = t; j < cnt; j += 128) {
            int c = g_cols[base + j];
            sc[j] = c;
            sd[j] = g_dinv[c];
        }
        __syncthreads();
        #pragma unroll 4
        for (int j = 0; j < cnt; j++) {
            const uint2* hv = (const uint2*)(h + (size_t)sc[j] * COUT);
            float s = sd[j];
            uint2 u = hv[t];
            float2 f0 = __half22float2(*(__half2*)&u.x);
            float2 f1 = __half22float2(*(__half2*)&u.y);
            acc.x = fmaf(s, f0.x, acc.x);
            acc.y = fmaf(s, f0.y, acc.y);
            acc.z = fmaf(s, f1.x, acc.z);
            acc.w = fmaf(s, f1.y, acc.w);
        }
        __syncthreads();
    }

    float dr = g_dinv[r];
    ((float4*)(out + (size_t)r * COUT))[t] =
        make_float4(dr * acc.x, dr * acc.y, dr * acc.z, dr * acc.w);
}

// ---------------- launch ----------------
extern "C" void kernel_launch(void* const* d_in, const int* in_sizes, int n_in,
                              void* d_out, int out_size) {
    const float* x    = (const float*)d_in[0];
    const void*  eidx = d_in[1];
    const float* W    = (const float*)d_in[2];
    const float* b    = (const float*)d_in[3];
    float* out = (float*)d_out;

    __half* h_ptr;
    cudaGetSymbolAddress((void**)&h_ptr, g_h);

    // 1. clear bitmap + degrees (+ dtype detect in block 0)
    k_clear<<<(int)(BM_WORDS / 4 / 256), 256>>>((const unsigned*)eidx);
    // 2. mark distinct edges + degree + rank + packed rc (1/thread)
    k_mark<<<(NITEMS + 255) / 256, 256>>>(eidx);
    // 3. scan -> CSR offsets, dinv (2 launches)
    k_scan_a<<<SCAN_BLKS, 256>>>();
    k_scan_c<<<SCAN_BLKS, 256>>>();
    // 4. fill CSR cols (no atomics, 1 item/thread)
    k_fill<<<(NITEMS + 255) / 256, 256>>>();
    // 5. h = x W^T + b (tensor cores, fp16 output)
    {
        dim3 grid(COUT / 128, NN / 128);  // (4, 64)
        k_gemm_tc<<<grid, 256>>>(x, W, b, h_ptr);
    }
    // 6. aggregate (fp16 gather, fp32 accumulate)
    k_agg<<<NN, 128>>>(h_ptr, out);
}

// round 11
// speedup vs baseline: 2.2875x; 1.3204x over previous
#include <cuda_runtime.h>
#include <cuda_bf16.h>
#include <cuda_fp16.h>
#include <stdint.h>

// Problem constants (fixed shapes)
#define NN      8192        // nodes
#define NE      262144      // edges
#define CIN     512
#define COUT    512
#define NITEMS  (NE + NN)   // 270336 = 264*1024
#define BM_WORDS ((size_t)NN * NN / 32)   // 8 MB bitmap
#define SCAN_BLKS 32        // 8192 / 256

// ---------------- device scratch (no allocations allowed) ----------------
__device__ unsigned g_bitmap[BM_WORDS];
__device__ int      g_deg[NN];
__device__ int      g_off[NN + 1];
__device__ float    g_dinv[NN];
__device__ int      g_cols[NITEMS];
__device__ unsigned short g_rank[NITEMS];    // slot within row; 0xFFFF = duplicate
__device__ unsigned g_rc[NITEMS];            // packed r | c<<16
__device__ int      g_bsum[SCAN_BLKS];
__device__ __half   g_h[(size_t)NN * COUT];  // 8 MB: h = xW^T + b (fp16)
__device__ int      g_is64;

// ---------------- clear bitmap + degree, fused dtype detection ----------------
__global__ void k_clear(const unsigned* __restrict__ e) {
    size_t i = (size_t)blockIdx.x * blockDim.x + threadIdx.x;
    if (i < BM_WORDS / 4) ((uint4*)g_bitmap)[i] = make_uint4(0u, 0u, 0u, 0u);
    if (i < NN) g_deg[i] = 0;
    if (blockIdx.x == 0) {
        unsigned v = (threadIdx.x < 128) ? e[threadIdx.x * 2 + 1] : 0u;
        int any = __syncthreads_or(v != 0u);
        if (threadIdx.x == 0) g_is64 = !any;
    }
}

__device__ __forceinline__ void edge_rc(const void* eidx, int is64, int i, int& r, int& c) {
    if (i < NE) {
        if (is64) {
            r = (int)((const long long*)eidx)[i];
            c = (int)((const long long*)eidx)[NE + i];
        } else {
            r = ((const int*)eidx)[i];
            c = ((const int*)eidx)[NE + i];
        }
    } else {
        r = c = i - NE;   // self loop
    }
}

// ---------------- mark distinct edges (1/thread; rank = slot within row) ----------------
__global__ __launch_bounds__(256)
void k_mark(const void* __restrict__ eidx) {
    int i = blockIdx.x * 256 + threadIdx.x;
    if (i >= NITEMS) return;
    int is64 = g_is64;
    int r, c;
    edge_rc(eidx, is64, i, r, c);
    size_t idx = (size_t)r * NN + c;
    unsigned bit = 1u << (idx & 31);
    unsigned old = atomicOr(&g_bitmap[idx >> 5], bit);
    g_rc[i] = (unsigned)r | ((unsigned)c << 16);
    unsigned short rk = 0xFFFFu;
    if (!(old & bit)) rk = (unsigned short)atomicAdd(&g_deg[r], 1);
    g_rank[i] = rk;
}

// ---------------- 2-phase multi-block scan ----------------
// Phase A: 32 blocks x 256 -> per-block degree sums
__global__ __launch_bounds__(256)
void k_scan_a() {
    __shared__ int ws[8];
    int i = blockIdx.x * 256 + threadIdx.x;
    int lane = threadIdx.x & 31, wid = threadIdx.x >> 5;
    int s = g_deg[i];
    #pragma unroll
    for (int off = 16; off > 0; off >>= 1) s += __shfl_down_sync(0xffffffffu, s, off);
    if (lane == 0) ws[wid] = s;
    __syncthreads();
    if (threadIdx.x == 0) {
        int t = 0;
        #pragma unroll
        for (int k = 0; k < 8; k++) t += ws[k];
        g_bsum[blockIdx.x] = t;
    }
}
// Phase C: 32 blocks x 256; warp 1 re-scans the 32 block sums locally,
// block-local exclusive scan + block offset.
__global__ __launch_bounds__(256)
void k_scan_c() {
    __shared__ int ws[8];
    __shared__ int sb32[32];
    int i = blockIdx.x * 256 + threadIdx.x;
    int lane = threadIdx.x & 31, wid = threadIdx.x >> 5;
    int v = g_deg[i];
    int x = v;
    #pragma unroll
    for (int off = 1; off < 32; off <<= 1) {
        int y = __shfl_up_sync(0xffffffffu, x, off);
        if (lane >= off) x += y;
    }
    if (lane == 31) ws[wid] = x;
    if (wid == 1) {   // warp 1 also scans the 32 global block sums
        int b = g_bsum[lane];
        int xx = b;
        #pragma unroll
        for (int off = 1; off < 32; off <<= 1) {
            int y = __shfl_up_sync(0xffffffffu, xx, off);
            if (lane >= off) xx += y;
        }
        sb32[lane] = xx;
        if (blockIdx.x == SCAN_BLKS - 1 && lane == 31) g_off[NN] = xx;
    }
    __syncthreads();
    if (wid == 0 && lane < 8) {
        int y = ws[lane];
        #pragma unroll
        for (int off = 1; off < 8; off <<= 1) {
            int z = __shfl_up_sync(0xffu, y, off);
            if (lane >= off) y += z;
        }
        ws[lane] = y;
    }
    __syncthreads();
    int boff = blockIdx.x ? sb32[blockIdx.x - 1] : 0;
    int base = (wid ? ws[wid - 1] : 0) + boff;
    g_off[i]  = base + x - v;
    g_dinv[i] = rsqrtf((float)v);   // deg >= 1 (self loop)
}

// ---------------- fill CSR columns (no atomics, no edge re-read) ----------------
__global__ __launch_bounds__(256)
void k_fill() {
    int i = blockIdx.x * 256 + threadIdx.x;
    if (i >= NITEMS) return;
    unsigned short rk = g_rank[i];
    if (rk == 0xFFFFu) return;
    unsigned u = g_rc[i];
    g_cols[g_off[u & 0xFFFFu] + rk] = (int)(u >> 16);
}

// ---------------- tensor GEMM: h = x W^T + b, single fp16 MMA ----------------
// fp16 quantization error ~2^-11 per product, random sign over K=512
// -> ~2e-4 dot-product rel error; total with fp16-h agg ~3e-4 (< 1e-3).
// Structure identical to the proven R3 kernel minus the 2 correction products.
#define BKP 40   // smem row stride in halfs (conflict-free for k-pair loads)

__device__ __forceinline__ void mma_fp16(float* c, const unsigned* a, const unsigned* b) {
    asm volatile(
        "mma.sync.aligned.m16n8k16.row.col.f32.f16.f16.f32 "
        "{%0,%1,%2,%3}, {%4,%5,%6,%7}, {%8,%9}, {%0,%1,%2,%3};"
        : "+f"(c[0]), "+f"(c[1]), "+f"(c[2]), "+f"(c[3])
        : "r"(a[0]), "r"(a[1]), "r"(a[2]), "r"(a[3]), "r"(b[0]), "r"(b[1]));
}

__global__ __launch_bounds__(256)
void k_gemm_tc(const float* __restrict__ A, const float* __restrict__ W,
               const float* __restrict__ bias, __half* __restrict__ C) {
    __shared__ __half sA[128 * BKP];
    __shared__ __half sB[128 * BKP];

    int tid = threadIdx.x;
    int m0 = blockIdx.y * 128;
    int n0 = blockIdx.x * 128;
    int lane = tid & 31, w = tid >> 5;
    int wm = (w & 1) * 64;       // warp row offset
    int wn = (w >> 1) * 32;      // warp col offset
    int g  = lane >> 2;          // 0..7
    int tg = lane & 3;           // 0..3

    float acc[4][4][4];
    #pragma unroll
    for (int mi = 0; mi < 4; mi++)
        #pragma unroll
        for (int ni = 0; ni < 4; ni++)
            #pragma unroll
            for (int q = 0; q < 4; q++) acc[mi][ni][q] = 0.f;

    int lr = tid >> 3;          // 0..31 (row within 32-row group)
    int lc = (tid & 7) * 4;     // k offset 0..28

    #pragma unroll 1
    for (int kt = 0; kt < CIN; kt += 32) {
        #pragma unroll
        for (int rr = 0; rr < 4; rr++) {
            int r = lr + rr * 32;
            float4 va = *(const float4*)(A + (size_t)(m0 + r) * CIN + kt + lc);
            float4 vb = *(const float4*)(W + (size_t)(n0 + r) * CIN + kt + lc);
            *(__half2*)&sA[r * BKP + lc]     = __floats2half2_rn(va.x, va.y);
            *(__half2*)&sA[r * BKP + lc + 2] = __floats2half2_rn(va.z, va.w);
            *(__half2*)&sB[r * BKP + lc]     = __floats2half2_rn(vb.x, vb.y);
            *(__half2*)&sB[r * BKP + lc + 2] = __floats2half2_rn(vb.z, vb.w);
        }
        __syncthreads();

        #pragma unroll
        for (int ks = 0; ks < 2; ks++) {
            int k0 = ks * 16 + tg * 2;
            unsigned af[4][4];
            #pragma unroll
            for (int mi = 0; mi < 4; mi++) {
                int r0 = wm + mi * 16 + g;
                af[mi][0] = *(unsigned*)&sA[r0 * BKP + k0];
                af[mi][1] = *(unsigned*)&sA[(r0 + 8) * BKP + k0];
                af[mi][2] = *(unsigned*)&sA[r0 * BKP + k0 + 8];
                af[mi][3] = *(unsigned*)&sA[(r0 + 8) * BKP + k0 + 8];
            }
            unsigned bf[4][2];
            #pragma unroll
            for (int ni = 0; ni < 4; ni++) {
                int c = wn + ni * 8 + g;
                bf[ni][0] = *(unsigned*)&sB[c * BKP + k0];
                bf[ni][1] = *(unsigned*)&sB[c * BKP + k0 + 8];
            }
            #pragma unroll
            for (int mi = 0; mi < 4; mi++)
                #pragma unroll
                for (int ni = 0; ni < 4; ni++)
                    mma_fp16(acc[mi][ni], af[mi], bf[ni]);
        }
        __syncthreads();
    }

    // epilogue: add bias (fp32), write h as fp16
    #pragma unroll
    for (int mi = 0; mi < 4; mi++) {
        int r0 = m0 + wm + mi * 16 + g;
        #pragma unroll
        for (int ni = 0; ni < 4; ni++) {
            int col = n0 + wn + ni * 8 + tg * 2;
            float b0 = bias[col], b1 = bias[col + 1];
            __half* p0 = C + (size_t)r0 * COUT + col;
            __half* p1 = C + (size_t)(r0 + 8) * COUT + col;
            *(__half2*)p0 = __floats2half2_rn(acc[mi][ni][0] + b0, acc[mi][ni][1] + b1);
            *(__half2*)p1 = __floats2half2_rn(acc[mi][ni][2] + b0, acc[mi][ni][3] + b1);
        }
    }
}

// ---------------- aggregation: out[r] = dinv[r] * sum_{c in N(r)} dinv[c] * h[c] ----------------
// h gathered as fp16 (half the L2 traffic), fp32 accumulation.
__global__ __launch_bounds__(128)
void k_agg(const __half* __restrict__ h, float* __restrict__ out) {
    __shared__ int   sc[256];
    __shared__ float sd[256];
    int r = blockIdx.x;
    int t = threadIdx.x;
    int beg = g_off[r], end = g_off[r + 1];
    float4 acc = make_float4(0.f, 0.f, 0.f, 0.f);

    for (int base = beg; base < end; base += 256) {
        int cnt = min(256, end - base);
        for (int j = t; j < cnt; j += 128) {
            int c = g_cols[base + j];
            sc[j] = c;
            sd[j] = g_dinv[c];
        }
        __syncthreads();
        #pragma unroll 4
        for (int j = 0; j < cnt; j++) {
            const uint2* hv = (const uint2*)(h + (size_t)sc[j] * COUT);
            float s = sd[j];
            uint2 u = hv[t];
            float2 f0 = __half22float2(*(__half2*)&u.x);
            float2 f1 = __half22float2(*(__half2*)&u.y);
            acc.x = fmaf(s, f0.x, acc.x);
            acc.y = fmaf(s, f0.y, acc.y);
            acc.z = fmaf(s, f1.x, acc.z);
            acc.w = fmaf(s, f1.y, acc.w);
        }
        __syncthreads();
    }

    float dr = g_dinv[r];
    ((float4*)(out + (size_t)r * COUT))[t] =
        make_float4(dr * acc.x, dr * acc.y, dr * acc.z, dr * acc.w);
}

// ---------------- launch ----------------
extern "C" void kernel_launch(void* const* d_in, const int* in_sizes, int n_in,
                              void* d_out, int out_size) {
    const float* x    = (const float*)d_in[0];
    const void*  eidx = d_in[1];
    const float* W    = (const float*)d_in[2];
    const float* b    = (const float*)d_in[3];
    float* out = (float*)d_out;

    __half* h_ptr;
    cudaGetSymbolAddress((void**)&h_ptr, g_h);

    // 1. clear bitmap + degrees (+ dtype detect in block 0)
    k_clear<<<(int)(BM_WORDS / 4 / 256), 256>>>((const unsigned*)eidx);
    // 2. mark distinct edges + degree + rank + packed rc (1/thread)
    k_mark<<<(NITEMS + 255) / 256, 256>>>(eidx);
    // 3. scan -> CSR offsets, dinv (2 launches)
    k_scan_a<<<SCAN_BLKS, 256>>>();
    k_scan_c<<<SCAN_BLKS, 256>>>();
    // 4. fill CSR cols (no atomics, 1 item/thread)
    k_fill<<<(NITEMS + 255) / 256, 256>>>();
    // 5. h = x W^T + b (single fp16 MMA)
    {
        dim3 grid(COUT / 128, NN / 128);  // (4, 64)
        k_gemm_tc<<<grid, 256>>>(x, W, b, h_ptr);
    }
    // 6. aggregate (fp16 gather, fp32 accumulate)
    k_agg<<<NN, 128>>>(h_ptr, out);
}

// round 12
// speedup vs baseline: 2.6386x; 1.1535x over previous
#include <cuda_runtime.h>
#include <cuda_bf16.h>
#include <cuda_fp16.h>
#include <stdint.h>

// Problem constants (fixed shapes)
#define NN      8192        // nodes
#define NE      262144      // edges
#define CIN     512
#define COUT    512
#define NITEMS  (NE + NN)   // 270336 = 264*1024
#define BM_WORDS ((size_t)NN * NN / 32)   // 8 MB bitmap
#define SCAN_BLKS 32        // 8192 / 256

// ---------------- device scratch (no allocations allowed) ----------------
__device__ unsigned g_bitmap[BM_WORDS];
__device__ int      g_deg[NN];
__device__ int      g_off[NN + 1];
__device__ float    g_dinv[NN];
__device__ int      g_cols[NITEMS];
__device__ unsigned short g_rank[NITEMS];    // slot within row; 0xFFFF = duplicate
__device__ unsigned g_rc[NITEMS];            // packed r | c<<16
__device__ int      g_bsum[SCAN_BLKS];
__device__ __half   g_h[(size_t)NN * COUT];  // 8 MB: h = xW^T + b (fp16)
__device__ int      g_is64;

// ---------------- clear bitmap + degree, fused dtype detection ----------------
__global__ void k_clear(const unsigned* __restrict__ e) {
    size_t i = (size_t)blockIdx.x * blockDim.x + threadIdx.x;
    if (i < BM_WORDS / 4) ((uint4*)g_bitmap)[i] = make_uint4(0u, 0u, 0u, 0u);
    if (i < NN) g_deg[i] = 0;
    if (blockIdx.x == 0) {
        unsigned v = (threadIdx.x < 128) ? e[threadIdx.x * 2 + 1] : 0u;
        int any = __syncthreads_or(v != 0u);
        if (threadIdx.x == 0) g_is64 = !any;
    }
}

__device__ __forceinline__ void edge_rc(const void* eidx, int is64, int i, int& r, int& c) {
    if (i < NE) {
        if (is64) {
            r = (int)((const long long*)eidx)[i];
            c = (int)((const long long*)eidx)[NE + i];
        } else {
            r = ((const int*)eidx)[i];
            c = ((const int*)eidx)[NE + i];
        }
    } else {
        r = c = i - NE;   // self loop
    }
}

// ---------------- mark distinct edges (1/thread; rank = slot within row) ----------------
__global__ __launch_bounds__(256)
void k_mark(const void* __restrict__ eidx) {
    int i = blockIdx.x * 256 + threadIdx.x;
    if (i >= NITEMS) return;
    int is64 = g_is64;
    int r, c;
    edge_rc(eidx, is64, i, r, c);
    size_t idx = (size_t)r * NN + c;
    unsigned bit = 1u << (idx & 31);
    unsigned old = atomicOr(&g_bitmap[idx >> 5], bit);
    g_rc[i] = (unsigned)r | ((unsigned)c << 16);
    unsigned short rk = 0xFFFFu;
    if (!(old & bit)) rk = (unsigned short)atomicAdd(&g_deg[r], 1);
    g_rank[i] = rk;
}

// ---------------- 2-phase multi-block scan ----------------
// Phase A: 32 blocks x 256 -> per-block degree sums
__global__ __launch_bounds__(256)
void k_scan_a() {
    __shared__ int ws[8];
    int i = blockIdx.x * 256 + threadIdx.x;
    int lane = threadIdx.x & 31, wid = threadIdx.x >> 5;
    int s = g_deg[i];
    #pragma unroll
    for (int off = 16; off > 0; off >>= 1) s += __shfl_down_sync(0xffffffffu, s, off);
    if (lane == 0) ws[wid] = s;
    __syncthreads();
    if (threadIdx.x == 0) {
        int t = 0;
        #pragma unroll
        for (int k = 0; k < 8; k++) t += ws[k];
        g_bsum[blockIdx.x] = t;
    }
}
// Phase C: 32 blocks x 256; warp 1 re-scans the 32 block sums locally,
// block-local exclusive scan + block offset.
__global__ __launch_bounds__(256)
void k_scan_c() {
    __shared__ int ws[8];
    __shared__ int sb32[32];
    int i = blockIdx.x * 256 + threadIdx.x;
    int lane = threadIdx.x & 31, wid = threadIdx.x >> 5;
    int v = g_deg[i];
    int x = v;
    #pragma unroll
    for (int off = 1; off < 32; off <<= 1) {
        int y = __shfl_up_sync(0xffffffffu, x, off);
        if (lane >= off) x += y;
    }
    if (lane == 31) ws[wid] = x;
    if (wid == 1) {   // warp 1 also scans the 32 global block sums
        int b = g_bsum[lane];
        int xx = b;
        #pragma unroll
        for (int off = 1; off < 32; off <<= 1) {
            int y = __shfl_up_sync(0xffffffffu, xx, off);
            if (lane >= off) xx += y;
        }
        sb32[lane] = xx;
        if (blockIdx.x == SCAN_BLKS - 1 && lane == 31) g_off[NN] = xx;
    }
    __syncthreads();
    if (wid == 0 && lane < 8) {
        int y = ws[lane];
        #pragma unroll
        for (int off = 1; off < 8; off <<= 1) {
            int z = __shfl_up_sync(0xffu, y, off);
            if (lane >= off) y += z;
        }
        ws[lane] = y;
    }
    __syncthreads();
    int boff = blockIdx.x ? sb32[blockIdx.x - 1] : 0;
    int base = (wid ? ws[wid - 1] : 0) + boff;
    g_off[i]  = base + x - v;
    g_dinv[i] = rsqrtf((float)v);   // deg >= 1 (self loop)
}

// ---------------- fill CSR columns (no atomics, no edge re-read) ----------------
__global__ __launch_bounds__(256)
void k_fill() {
    int i = blockIdx.x * 256 + threadIdx.x;
    if (i >= NITEMS) return;
    unsigned short rk = g_rank[i];
    if (rk == 0xFFFFu) return;
    unsigned u = g_rc[i];
    g_cols[g_off[u & 0xFFFFu] + rk] = (int)(u >> 16);
}

// ---------------- tensor GEMM: h = x W^T + b, single fp16 MMA ----------------
#define BKP 40   // smem row stride in halfs (conflict-free for k-pair loads)

__device__ __forceinline__ void mma_fp16(float* c, const unsigned* a, const unsigned* b) {
    asm volatile(
        "mma.sync.aligned.m16n8k16.row.col.f32.f16.f16.f32 "
        "{%0,%1,%2,%3}, {%4,%5,%6,%7}, {%8,%9}, {%0,%1,%2,%3};"
        : "+f"(c[0]), "+f"(c[1]), "+f"(c[2]), "+f"(c[3])
        : "r"(a[0]), "r"(a[1]), "r"(a[2]), "r"(a[3]), "r"(b[0]), "r"(b[1]));
}

__global__ __launch_bounds__(256)
void k_gemm_tc(const float* __restrict__ A, const float* __restrict__ W,
               const float* __restrict__ bias, __half* __restrict__ C) {
    __shared__ __half sA[128 * BKP];
    __shared__ __half sB[128 * BKP];

    int tid = threadIdx.x;
    int m0 = blockIdx.y * 128;
    int n0 = blockIdx.x * 128;
    int lane = tid & 31, w = tid >> 5;
    int wm = (w & 1) * 64;       // warp row offset
    int wn = (w >> 1) * 32;      // warp col offset
    int g  = lane >> 2;          // 0..7
    int tg = lane & 3;           // 0..3

    float acc[4][4][4];
    #pragma unroll
    for (int mi = 0; mi < 4; mi++)
        #pragma unroll
        for (int ni = 0; ni < 4; ni++)
            #pragma unroll
            for (int q = 0; q < 4; q++) acc[mi][ni][q] = 0.f;

    int lr = tid >> 3;          // 0..31 (row within 32-row group)
    int lc = (tid & 7) * 4;     // k offset 0..28

    #pragma unroll 1
    for (int kt = 0; kt < CIN; kt += 32) {
        #pragma unroll
        for (int rr = 0; rr < 4; rr++) {
            int r = lr + rr * 32;
            float4 va = *(const float4*)(A + (size_t)(m0 + r) * CIN + kt + lc);
            float4 vb = *(const float4*)(W + (size_t)(n0 + r) * CIN + kt + lc);
            *(__half2*)&sA[r * BKP + lc]     = __floats2half2_rn(va.x, va.y);
            *(__half2*)&sA[r * BKP + lc + 2] = __floats2half2_rn(va.z, va.w);
            *(__half2*)&sB[r * BKP + lc]     = __floats2half2_rn(vb.x, vb.y);
            *(__half2*)&sB[r * BKP + lc + 2] = __floats2half2_rn(vb.z, vb.w);
        }
        __syncthreads();

        #pragma unroll
        for (int ks = 0; ks < 2; ks++) {
            int k0 = ks * 16 + tg * 2;
            unsigned af[4][4];
            #pragma unroll
            for (int mi = 0; mi < 4; mi++) {
                int r0 = wm + mi * 16 + g;
                af[mi][0] = *(unsigned*)&sA[r0 * BKP + k0];
                af[mi][1] = *(unsigned*)&sA[(r0 + 8) * BKP + k0];
                af[mi][2] = *(unsigned*)&sA[r0 * BKP + k0 + 8];
                af[mi][3] = *(unsigned*)&sA[(r0 + 8) * BKP + k0 + 8];
            }
            unsigned bf[4][2];
            #pragma unroll
            for (int ni = 0; ni < 4; ni++) {
                int c = wn + ni * 8 + g;
                bf[ni][0] = *(unsigned*)&sB[c * BKP + k0];
                bf[ni][1] = *(unsigned*)&sB[c * BKP + k0 + 8];
            }
            #pragma unroll
            for (int mi = 0; mi < 4; mi++)
                #pragma unroll
                for (int ni = 0; ni < 4; ni++)
                    mma_fp16(acc[mi][ni], af[mi], bf[ni]);
        }
        __syncthreads();
    }

    // epilogue: add bias (fp32), write h as fp16
    #pragma unroll
    for (int mi = 0; mi < 4; mi++) {
        int r0 = m0 + wm + mi * 16 + g;
        #pragma unroll
        for (int ni = 0; ni < 4; ni++) {
            int col = n0 + wn + ni * 8 + tg * 2;
            float b0 = bias[col], b1 = bias[col + 1];
            __half* p0 = C + (size_t)r0 * COUT + col;
            __half* p1 = C + (size_t)(r0 + 8) * COUT + col;
            *(__half2*)p0 = __floats2half2_rn(acc[mi][ni][0] + b0, acc[mi][ni][1] + b1);
            *(__half2*)p1 = __floats2half2_rn(acc[mi][ni][2] + b0, acc[mi][ni][3] + b1);
        }
    }
}

// ---------------- aggregation: out[r] = dinv[r] * sum_{c in N(r)} dinv[c] * h[c] ----------------
__global__ __launch_bounds__(128)
void k_agg(const __half* __restrict__ h, float* __restrict__ out) {
    __shared__ int   sc[256];
    __shared__ float sd[256];
    int r = blockIdx.x;
    int t = threadIdx.x;
    int beg = g_off[r], end = g_off[r + 1];
    float4 acc = make_float4(0.f, 0.f, 0.f, 0.f);

    for (int base = beg; base < end; base += 256) {
        int cnt = min(256, end - base);
        for (int j = t; j < cnt; j += 128) {
            int c = g_cols[base + j];
            sc[j] = c;
            sd[j] = g_dinv[c];
        }
        __syncthreads();
        #pragma unroll 4
        for (int j = 0; j < cnt; j++) {
            const uint2* hv = (const uint2*)(h + (size_t)sc[j] * COUT);
            float s = sd[j];
            uint2 u = hv[t];
            float2 f0 = __half22float2(*(__half2*)&u.x);
            float2 f1 = __half22float2(*(__half2*)&u.y);
            acc.x = fmaf(s, f0.x, acc.x);
            acc.y = fmaf(s, f0.y, acc.y);
            acc.z = fmaf(s, f1.x, acc.z);
            acc.w = fmaf(s, f1.y, acc.w);
        }
        __syncthreads();
    }

    float dr = g_dinv[r];
    ((float4*)(out + (size_t)r * COUT))[t] =
        make_float4(dr * acc.x, dr * acc.y, dr * acc.z, dr * acc.w);
}

// ---------------- launch: fork GEMM || edge pipeline, join before agg ----------------
extern "C" void kernel_launch(void* const* d_in, const int* in_sizes, int n_in,
                              void* d_out, int out_size) {
    const float* x    = (const float*)d_in[0];
    const void*  eidx = d_in[1];
    const float* W    = (const float*)d_in[2];
    const float* b    = (const float*)d_in[3];
    float* out = (float*)d_out;

    __half* h_ptr;
    cudaGetSymbolAddress((void**)&h_ptr, g_h);

    // Side stream + events for graph fork/join. Host-side objects only (no
    // device memory). kernel_launch runs twice (correctness + capture), so the
    // few leaked handles are harmless; destroying them mid-capture would be the
    // risky path.
    cudaStream_t s2;
    cudaStreamCreateWithFlags(&s2, cudaStreamNonBlocking);
    cudaEvent_t eFork, eJoin;
    cudaEventCreateWithFlags(&eFork, cudaEventDisableTiming);
    cudaEventCreateWithFlags(&eJoin, cudaEventDisableTiming);

    // fork: GEMM branch (depends only on x, W, b)
    cudaEventRecord(eFork, 0);
    cudaStreamWaitEvent(s2, eFork, 0);
    {
        dim3 grid(COUT / 128, NN / 128);  // (4, 64)
        k_gemm_tc<<<grid, 256, 0, s2>>>(x, W, b, h_ptr);
    }
    cudaEventRecord(eJoin, s2);

    // edge pipeline branch on the origin stream (depends only on edge_index)
    k_clear<<<(int)(BM_WORDS / 4 / 256), 256>>>((const unsigned*)eidx);
    k_mark<<<(NITEMS + 255) / 256, 256>>>(eidx);
    k_scan_a<<<SCAN_BLKS, 256>>>();
    k_scan_c<<<SCAN_BLKS, 256>>>();
    k_fill<<<(NITEMS + 255) / 256, 256>>>();

    // join: agg needs both h and the CSR
    cudaStreamWaitEvent(0, eJoin, 0);
    k_agg<<<NN, 128>>>(h_ptr, out);
}

// round 13
// speedup vs baseline: 2.8651x; 1.0858x over previous
#include <cuda_runtime.h>
#include <cuda_bf16.h>
#include <cuda_fp16.h>
#include <stdint.h>

// Problem constants (fixed shapes)
#define NN      8192        // nodes
#define NE      262144      // edges
#define CIN     512
#define COUT    512
#define NITEMS  (NE + NN)   // 270336 = 264*1024
#define BM_WORDS ((size_t)NN * NN / 32)   // 8 MB bitmap
#define SCAN_BLKS 32        // 8192 / 256
#define SCAN_FLAG (1 << 30)

// ---------------- device scratch (no allocations allowed) ----------------
// Invariant: g_bitmap is all-zero and g_deg/g_bsum are zero at the START of
// every kernel_launch run. Established by static zero-init for run #1 and by
// k_cleanup at the end of every run thereafter.
__device__ unsigned g_bitmap[BM_WORDS];
__device__ int      g_deg[NN];
__device__ int      g_off[NN + 1];
__device__ float    g_dinv[NN];
__device__ int      g_cols[NITEMS];
__device__ unsigned short g_rank[NITEMS];    // slot within row; 0xFFFF = duplicate
__device__ unsigned g_rc[NITEMS];            // packed r | c<<16
__device__ int      g_bsum[SCAN_BLKS];
__device__ __half   g_h[(size_t)NN * COUT];  // 8 MB: h = xW^T + b (fp16)

__device__ __forceinline__ void edge_rc(const void* eidx, int is64, int i, int& r, int& c) {
    if (i < NE) {
        if (is64) {
            r = (int)((const long long*)eidx)[i];
            c = (int)((const long long*)eidx)[NE + i];
        } else {
            r = ((const int*)eidx)[i];
            c = ((const int*)eidx)[NE + i];
        }
    } else {
        r = c = i - NE;   // self loop
    }
}

// ---------------- mark distinct edges (inline dtype ballot) ----------------
// dtype: if int64 (LE), high words of ids are 0 (ids < 8192). If int32, the
// odd words are random ids: P(128 random ids all zero) ~ 8192^-128 ~ 0.
__global__ __launch_bounds__(256)
void k_mark(const void* __restrict__ eidx) {
    const unsigned* e32 = (const unsigned*)eidx;
    unsigned hv = (threadIdx.x < 128) ? e32[threadIdx.x * 2 + 1] : 0u;
    int is64 = !__syncthreads_or(hv != 0u);

    int i = blockIdx.x * 256 + threadIdx.x;
    if (i >= NITEMS) return;
    int r, c;
    edge_rc(eidx, is64, i, r, c);
    size_t idx = (size_t)r * NN + c;
    unsigned bit = 1u << (idx & 31);
    unsigned old = atomicOr(&g_bitmap[idx >> 5], bit);
    g_rc[i] = (unsigned)r | ((unsigned)c << 16);
    unsigned short rk = 0xFFFFu;
    if (!(old & bit)) rk = (unsigned short)atomicAdd(&g_deg[r], 1);
    g_rank[i] = rk;
}

// ---------------- single-kernel spin-publish scan ----------------
// 32 blocks x 256. Each block: local exclusive scan of its 256 degrees,
// publish block total with a valid flag, poll all 32 totals, add prefix.
// 32 blocks always co-resident (<< 148 SMs) -> progress guaranteed.
__global__ __launch_bounds__(256)
void k_scan() {
    __shared__ int ws[8];
    __shared__ int sb32[32];
    int t = threadIdx.x, b = blockIdx.x;
    int i = b * 256 + t;
    int lane = t & 31, wid = t >> 5;
    int v = g_deg[i];
    int x = v;
    #pragma unroll
    for (int off = 1; off < 32; off <<= 1) {
        int y = __shfl_up_sync(0xffffffffu, x, off);
        if (lane >= off) x += y;
    }
    if (lane == 31) ws[wid] = x;
    __syncthreads();
    if (wid == 0 && lane < 8) {
        int y = ws[lane];
        #pragma unroll
        for (int off = 1; off < 8; off <<= 1) {
            int z = __shfl_up_sync(0xffu, y, off);
            if (lane >= off) y += z;
        }
        ws[lane] = y;
    }
    __syncthreads();
    int btotal = ws[7];
    if (t == 0) atomicExch(&g_bsum[b], btotal | SCAN_FLAG);
    if (wid == 0) {
        int s;
        do { s = (int)atomicAdd((unsigned*)&g_bsum[lane], 0u); } while (!(s & SCAN_FLAG));
        s &= ~SCAN_FLAG;
        int xx = s;
        #pragma unroll
        for (int off = 1; off < 32; off <<= 1) {
            int y = __shfl_up_sync(0xffffffffu, xx, off);
            if (lane >= off) xx += y;
        }
        sb32[lane] = xx;
        if (b == SCAN_BLKS - 1 && lane == 31) g_off[NN] = xx;
    }
    __syncthreads();
    int boff = b ? sb32[b - 1] : 0;
    int base = (wid ? ws[wid - 1] : 0) + boff;
    g_off[i]  = base + x - v;
    g_dinv[i] = rsqrtf((float)v);   // deg >= 1 (self loop)
}

// ---------------- fill CSR columns (no atomics, no edge re-read) ----------------
__global__ __launch_bounds__(256)
void k_fill() {
    int i = blockIdx.x * 256 + threadIdx.x;
    if (i >= NITEMS) return;
    unsigned short rk = g_rank[i];
    if (rk == 0xFFFFu) return;
    unsigned u = g_rc[i];
    g_cols[g_off[u & 0xFFFFu] + rk] = (int)(u >> 16);
}

// ---------------- cleanup: re-establish the zero invariant for next run ----------------
// Clears exactly the bits this run set (via g_rc), zeroes deg and bsum.
// Runs overlapped with fill/agg; must follow k_scan (last deg/bsum reader).
__global__ __launch_bounds__(256)
void k_cleanup() {
    int i = blockIdx.x * 256 + threadIdx.x;
    if (i < NITEMS) {
        unsigned u = g_rc[i];
        size_t idx = (size_t)(u & 0xFFFFu) * NN + (u >> 16);
        atomicAnd(&g_bitmap[idx >> 5], ~(1u << (idx & 31)));
    }
    if (i < NN) g_deg[i] = 0;
    if (i < SCAN_BLKS) g_bsum[i] = 0;
}

// ---------------- tensor GEMM: h = x W^T + b, single fp16 MMA ----------------
#define BKP 40   // smem row stride in halfs (conflict-free for k-pair loads)

__device__ __forceinline__ void mma_fp16(float* c, const unsigned* a, const unsigned* b) {
    asm volatile(
        "mma.sync.aligned.m16n8k16.row.col.f32.f16.f16.f32 "
        "{%0,%1,%2,%3}, {%4,%5,%6,%7}, {%8,%9}, {%0,%1,%2,%3};"
        : "+f"(c[0]), "+f"(c[1]), "+f"(c[2]), "+f"(c[3])
        : "r"(a[0]), "r"(a[1]), "r"(a[2]), "r"(a[3]), "r"(b[0]), "r"(b[1]));
}

__global__ __launch_bounds__(256)
void k_gemm_tc(const float* __restrict__ A, const float* __restrict__ W,
               const float* __restrict__ bias, __half* __restrict__ C) {
    __shared__ __half sA[128 * BKP];
    __shared__ __half sB[128 * BKP];

    int tid = threadIdx.x;
    int m0 = blockIdx.y * 128;
    int n0 = blockIdx.x * 128;
    int lane = tid & 31, w = tid >> 5;
    int wm = (w & 1) * 64;       // warp row offset
    int wn = (w >> 1) * 32;      // warp col offset
    int g  = lane >> 2;          // 0..7
    int tg = lane & 3;           // 0..3

    float acc[4][4][4];
    #pragma unroll
    for (int mi = 0; mi < 4; mi++)
        #pragma unroll
        for (int ni = 0; ni < 4; ni++)
            #pragma unroll
            for (int q = 0; q < 4; q++) acc[mi][ni][q] = 0.f;

    int lr = tid >> 3;          // 0..31 (row within 32-row group)
    int lc = (tid & 7) * 4;     // k offset 0..28

    #pragma unroll 1
    for (int kt = 0; kt < CIN; kt += 32) {
        #pragma unroll
        for (int rr = 0; rr < 4; rr++) {
            int r = lr + rr * 32;
            float4 va = *(const float4*)(A + (size_t)(m0 + r) * CIN + kt + lc);
            float4 vb = *(const float4*)(W + (size_t)(n0 + r) * CIN + kt + lc);
            *(__half2*)&sA[r * BKP + lc]     = __floats2half2_rn(va.x, va.y);
            *(__half2*)&sA[r * BKP + lc + 2] = __floats2half2_rn(va.z, va.w);
            *(__half2*)&sB[r * BKP + lc]     = __floats2half2_rn(vb.x, vb.y);
            *(__half2*)&sB[r * BKP + lc + 2] = __floats2half2_rn(vb.z, vb.w);
        }
        __syncthreads();

        #pragma unroll
        for (int ks = 0; ks < 2; ks++) {
            int k0 = ks * 16 + tg * 2;
            unsigned af[4][4];
            #pragma unroll
            for (int mi = 0; mi < 4; mi++) {
                int r0 = wm + mi * 16 + g;
                af[mi][0] = *(unsigned*)&sA[r0 * BKP + k0];
                af[mi][1] = *(unsigned*)&sA[(r0 + 8) * BKP + k0];
                af[mi][2] = *(unsigned*)&sA[r0 * BKP + k0 + 8];
                af[mi][3] = *(unsigned*)&sA[(r0 + 8) * BKP + k0 + 8];
            }
            unsigned bf[4][2];
            #pragma unroll
            for (int ni = 0; ni < 4; ni++) {
                int c = wn + ni * 8 + g;
                bf[ni][0] = *(unsigned*)&sB[c * BKP + k0];
                bf[ni][1] = *(unsigned*)&sB[c * BKP + k0 + 8];
            }
            #pragma unroll
            for (int mi = 0; mi < 4; mi++)
                #pragma unroll
                for (int ni = 0; ni < 4; ni++)
                    mma_fp16(acc[mi][ni], af[mi], bf[ni]);
        }
        __syncthreads();
    }

    // epilogue: add bias (fp32), write h as fp16
    #pragma unroll
    for (int mi = 0; mi < 4; mi++) {
        int r0 = m0 + wm + mi * 16 + g;
        #pragma unroll
        for (int ni = 0; ni < 4; ni++) {
            int col = n0 + wn + ni * 8 + tg * 2;
            float b0 = bias[col], b1 = bias[col + 1];
            __half* p0 = C + (size_t)r0 * COUT + col;
            __half* p1 = C + (size_t)(r0 + 8) * COUT + col;
            *(__half2*)p0 = __floats2half2_rn(acc[mi][ni][0] + b0, acc[mi][ni][1] + b1);
            *(__half2*)p1 = __floats2half2_rn(acc[mi][ni][2] + b0, acc[mi][ni][3] + b1);
        }
    }
}

// ---------------- aggregation: out[r] = dinv[r] * sum_{c in N(r)} dinv[c] * h[c] ----------------
__global__ __launch_bounds__(128)
void k_agg(const __half* __restrict__ h, float* __restrict__ out) {
    __shared__ int   sc[256];
    __shared__ float sd[256];
    int r = blockIdx.x;
    int t = threadIdx.x;
    int beg = g_off[r], end = g_off[r + 1];
    float4 acc = make_float4(0.f, 0.f, 0.f, 0.f);

    for (int base = beg; base < end; base += 256) {
        int cnt = min(256, end - base);
        for (int j = t; j < cnt; j += 128) {
            int c = g_cols[base + j];
            sc[j] = c;
            sd[j] = g_dinv[c];
        }
        __syncthreads();
        #pragma unroll 4
        for (int j = 0; j < cnt; j++) {
            const uint2* hv = (const uint2*)(h + (size_t)sc[j] * COUT);
            float s = sd[j];
            uint2 u = hv[t];
            float2 f0 = __half22float2(*(__half2*)&u.x);
            float2 f1 = __half22float2(*(__half2*)&u.y);
            acc.x = fmaf(s, f0.x, acc.x);
            acc.y = fmaf(s, f0.y, acc.y);
            acc.z = fmaf(s, f1.x, acc.z);
            acc.w = fmaf(s, f1.y, acc.w);
        }
        __syncthreads();
    }

    float dr = g_dinv[r];
    ((float4*)(out + (size_t)r * COUT))[t] =
        make_float4(dr * acc.x, dr * acc.y, dr * acc.z, dr * acc.w);
}

// ---------------- launch: fork GEMM || edge pipeline; cleanup overlaps agg ----------------
extern "C" void kernel_launch(void* const* d_in, const int* in_sizes, int n_in,
                              void* d_out, int out_size) {
    const float* x    = (const float*)d_in[0];
    const void*  eidx = d_in[1];
    const float* W    = (const float*)d_in[2];
    const float* b    = (const float*)d_in[3];
    float* out = (float*)d_out;

    __half* h_ptr;
    cudaGetSymbolAddress((void**)&h_ptr, g_h);

    // Host-side stream/event objects only; intentionally not destroyed
    // (kernel_launch runs twice — correctness + capture).
    cudaStream_t s2;
    cudaStreamCreateWithFlags(&s2, cudaStreamNonBlocking);
    cudaEvent_t eFork, eGemm, eScan, eClean;
    cudaEventCreateWithFlags(&eFork,  cudaEventDisableTiming);
    cudaEventCreateWithFlags(&eGemm,  cudaEventDisableTiming);
    cudaEventCreateWithFlags(&eScan,  cudaEventDisableTiming);
    cudaEventCreateWithFlags(&eClean, cudaEventDisableTiming);

    // fork: GEMM branch (depends only on x, W, b)
    cudaEventRecord(eFork, 0);
    cudaStreamWaitEvent(s2, eFork, 0);
    {
        dim3 grid(COUT / 128, NN / 128);  // (4, 64)
        k_gemm_tc<<<grid, 256, 0, s2>>>(x, W, b, h_ptr);
    }
    cudaEventRecord(eGemm, s2);

    // edge pipeline on origin stream (bitmap/deg/bsum are pre-zeroed by invariant)
    k_mark<<<(NITEMS + 255) / 256, 256>>>(eidx);
    k_scan<<<SCAN_BLKS, 256>>>();
    cudaEventRecord(eScan, 0);
    k_fill<<<(NITEMS + 255) / 256, 256>>>();

    // cleanup on s2 after scan (last deg/bsum reader) — overlaps fill + agg
    cudaStreamWaitEvent(s2, eScan, 0);
    k_cleanup<<<(NITEMS + 255) / 256, 256, 0, s2>>>();
    cudaEventRecord(eClean, s2);

    // join: agg needs both h (GEMM) and the CSR (fill)
    cudaStreamWaitEvent(0, eGemm, 0);
    k_agg<<<NN, 128>>>(h_ptr, out);

    // join cleanup so the captured graph is fully joined at end
    cudaStreamWaitEvent(0, eClean, 0);
}